// round 13
// baseline (speedup 1.0000x reference)
#include <cuda_runtime.h>
#include <cuda_bf16.h>
#include <math.h>
#include <stdint.h>

#define BATCH   1024
#define NTOK    64
#define DIM     512
#define HEADS   16
#define HDIM    32
#define NW      64
#define ROWS    (BATCH * NTOK)      // 65536
#define QKVCOLS (3 * DIM)           // 1536

// ---------------- device scratch ----------------
__device__ __align__(16) float         g_qkv[(size_t)ROWS * QKVCOLS];
__device__ __align__(16) __nv_bfloat16 g_xh[(size_t)ROWS * DIM];
__device__ __align__(16) __nv_bfloat16 g_xl[(size_t)ROWS * DIM];
__device__ __align__(16) __nv_bfloat16 g_wh[(size_t)QKVCOLS * DIM];
__device__ __align__(16) __nv_bfloat16 g_wl[(size_t)QKVCOLS * DIM];
__device__ __align__(16) __nv_bfloat16 g_ph[(size_t)DIM * DIM];
__device__ __align__(16) __nv_bfloat16 g_pl[(size_t)DIM * DIM];
__device__ __align__(16) __nv_bfloat16 g_aoh[(size_t)ROWS * DIM];
__device__ __align__(16) __nv_bfloat16 g_aol[(size_t)ROWS * DIM];
__device__ float g_bias_table[225 * HEADS];
__device__ float g_rel_bias[HEADS * NTOK * NTOK];
__device__ float g_scale[HEADS];

// ---------------- helpers ----------------
__device__ __forceinline__ uint32_t smem_u32(const void* p) {
    uint32_t a;
    asm("{ .reg .u64 t; cvta.to.shared.u64 t, %1; cvt.u32.u64 %0, t; }" : "=r"(a) : "l"(p));
    return a;
}

#define LDSM4(r0,r1,r2,r3, addr) \
    asm volatile("ldmatrix.sync.aligned.m8n8.x4.shared.b16 {%0,%1,%2,%3}, [%4];" \
        : "=r"(r0),"=r"(r1),"=r"(r2),"=r"(r3) : "r"(addr))

#define MMA_BF16(d, a, b) \
    asm volatile("mma.sync.aligned.m16n8k16.row.col.f32.bf16.bf16.f32 " \
        "{%0,%1,%2,%3}, {%4,%5,%6,%7}, {%8,%9}, {%0,%1,%2,%3};" \
        : "+f"(d[0]),"+f"(d[1]),"+f"(d[2]),"+f"(d[3]) \
        : "r"(a[0]),"r"(a[1]),"r"(a[2]),"r"(a[3]),"r"(b[0]),"r"(b[1]))

#define CP16(dst, src) \
    asm volatile("cp.async.ca.shared.global [%0], [%1], 16;" :: "r"(dst), "l"(src))
#define CP_COMMIT() asm volatile("cp.async.commit_group;" ::: "memory")
#define CP_WAIT0()  asm volatile("cp.async.wait_group 0;" ::: "memory")

// ---- packed f32x2 (FFMA2) ----
typedef unsigned long long u64t;
__device__ __forceinline__ u64t pk2(float lo, float hi) {
    u64t r; asm("mov.b64 %0, {%1, %2};" : "=l"(r) : "f"(lo), "f"(hi)); return r;
}
__device__ __forceinline__ void fma2(u64t& d, u64t a, u64t b) {
    asm("fma.rn.f32x2 %0, %1, %2, %0;" : "+l"(d) : "l"(a), "l"(b));
}
__device__ __forceinline__ float2 upk2(u64t v) {
    float2 r; asm("mov.b64 {%0, %1}, %2;" : "=f"(r.x), "=f"(r.y) : "l"(v)); return r;
}

// ---------------- fp32 -> bf16 hi/lo split ----------------
__global__ void split_f32(const float* __restrict__ in,
                          __nv_bfloat16* __restrict__ hi,
                          __nv_bfloat16* __restrict__ lo, int n4)
{
    int i = blockIdx.x * blockDim.x + threadIdx.x;
    if (i >= n4) return;
    float4 v = ((const float4*)in)[i];
    __nv_bfloat16 h[4], l[4];
    float x[4] = {v.x, v.y, v.z, v.w};
    #pragma unroll
    for (int j = 0; j < 4; j++) {
        h[j] = __float2bfloat16(x[j]);
        l[j] = __float2bfloat16(x[j] - __bfloat162float(h[j]));
    }
    ((uint2*)hi)[i] = *(uint2*)h;
    ((uint2*)lo)[i] = *(uint2*)l;
}

// ---------------- CPB MLP ----------------
__global__ void cpb_mlp_kernel(const float* __restrict__ tbl,
                               const float* __restrict__ w1,
                               const float* __restrict__ b1,
                               const float* __restrict__ w2)
{
    int i = blockIdx.x, j = threadIdx.x;
    __shared__ float hid[512];
    float hv = tbl[i*2+0] * w1[j*2+0] + tbl[i*2+1] * w1[j*2+1] + b1[j];
    hid[j] = fmaxf(hv, 0.0f);
    __syncthreads();
    int warp = j >> 5, lane = j & 31;
    float s = 0.0f;
    #pragma unroll
    for (int c = lane; c < 512; c += 32) s += hid[c] * w2[warp*512 + c];
    #pragma unroll
    for (int off = 16; off > 0; off >>= 1) s += __shfl_xor_sync(0xffffffffu, s, off);
    if (lane == 0) g_bias_table[i*HEADS + warp] = s;
}

__global__ void cpb_expand_kernel(const int* __restrict__ idx,
                                  const float* __restrict__ logit_scale)
{
    int g = blockIdx.x * 256 + threadIdx.x;
    int h = g >> 12, nm = g & 4095;
    float v = g_bias_table[idx[nm]*HEADS + h];
    g_rel_bias[g] = 16.0f / (1.0f + expf(-v));
    if (g < HEADS) g_scale[g] = expf(fminf(logit_scale[g], 4.60517018598809136804f));
}

// ---------------------------------------------------------------------------
// split-bf16 GEMM (NT): C[M,N] = (Ah+Al)[M,K] @ (Bh+Bl)[N,K]^T + bias
// BM=BN=128, BK=64, K=512. 512 thr = 16 warps (4m x 4n), warp 32x32.
// 2-stage cp.async (wait_group 0 before barrier; next load overlaps compute),
// fragment double-buffering across the 4 ks-groups. Rows padded to 144B
// (144 mod 128 = 16 -> conflict-free LDSM phases).
// ---------------------------------------------------------------------------
#define ROWB 144
#define AT_SZ (128 * ROWB)       // 18432 per matrix
#define STG (4 * AT_SZ)          // 73728
#define GEMM_SMEM (2 * STG)      // 147456

template <int MODE>   // 0: qkv bias (q|0|v), 1: proj bias
__global__ __launch_bounds__(512, 1) void gemm_bf16_128(
    const __nv_bfloat16* __restrict__ Ah, const __nv_bfloat16* __restrict__ Al,
    const __nv_bfloat16* __restrict__ Bh, const __nv_bfloat16* __restrict__ Bl,
    const float* __restrict__ bias0, const float* __restrict__ bias1,
    float* __restrict__ C, int N)
{
    extern __shared__ char smem[];

    const int tid  = threadIdx.x;
    const int bm   = blockIdx.y * 128;
    const int bn   = blockIdx.x * 128;
    const int wid  = tid >> 5, lane = tid & 31;
    const int wm   = (wid & 3) * 32;
    const int wn   = (wid >> 2) * 32;

    const uint32_t sbase = smem_u32(smem);

    float acc[2][4][4];
    #pragma unroll
    for (int a = 0; a < 2; a++)
        #pragma unroll
        for (int b = 0; b < 4; b++)
            #pragma unroll
            for (int c = 0; c < 4; c++) acc[a][b][c] = 0.0f;

    // loader: per matrix, thread -> row = tid>>2, two 16B chunks (q*2, q*2+1)
    const int lrow = tid >> 2;       // 0..127
    const int lq   = tid & 3;        // 0..3
    auto load_stage = [&](int kt, int buf) {
        const uint32_t sb = sbase + buf * STG;
        #pragma unroll
        for (int j = 0; j < 2; j++) {
            const int ch = lq * 2 + j;                         // 0..7
            const size_t ga = (size_t)(bm + lrow) * 512 + kt * 64 + ch * 8;
            const size_t gb = (size_t)(bn + lrow) * 512 + kt * 64 + ch * 8;
            const uint32_t d = sb + (uint32_t)(lrow * ROWB + ch * 16);
            CP16(d,           (const char*)Ah + ga * 2);
            CP16(d +   AT_SZ, (const char*)Al + ga * 2);
            CP16(d + 2*AT_SZ, (const char*)Bh + gb * 2);
            CP16(d + 3*AT_SZ, (const char*)Bl + gb * 2);
        }
        CP_COMMIT();
    };

    // fragment loader for one ks group (16 cols = 32 bytes at kb)
    auto ldfrags = [&](uint32_t sb, int ks,
                       uint32_t (&ah)[2][4], uint32_t (&al)[2][4],
                       uint32_t (&bh)[4][2], uint32_t (&bl)[4][2]) {
        const int kb = ks * 32;   // byte offset of this 16-col group
        #pragma unroll
        for (int mt = 0; mt < 2; mt++) {
            int row = wm + mt*16 + (lane & 15);
            uint32_t off = (uint32_t)(row*ROWB + kb + (lane >> 4) * 16);
            LDSM4(ah[mt][0], ah[mt][1], ah[mt][2], ah[mt][3], sb + off);
            LDSM4(al[mt][0], al[mt][1], al[mt][2], al[mt][3], sb + AT_SZ + off);
        }
        #pragma unroll
        for (int np = 0; np < 2; np++) {
            int g = lane >> 3;
            int row = wn + np*16 + (lane & 7) + ((g >> 1) & 1) * 8;
            uint32_t off = (uint32_t)(row*ROWB + kb + (g & 1) * 16);
            LDSM4(bh[2*np][0], bh[2*np][1], bh[2*np+1][0], bh[2*np+1][1], sb + 2*AT_SZ + off);
            LDSM4(bl[2*np][0], bl[2*np][1], bl[2*np+1][0], bl[2*np+1][1], sb + 3*AT_SZ + off);
        }
    };

    load_stage(0, 0);

    for (int kt = 0; kt < 8; kt++) {
        CP_WAIT0();
        __syncthreads();
        if (kt + 1 < 8) load_stage(kt + 1, (kt + 1) & 1);   // overlaps compute

        const uint32_t sb = sbase + (kt & 1) * STG;
        uint32_t ah[2][2][4], al[2][2][4], bh[2][4][2], bl[2][4][2];
        ldfrags(sb, 0, ah[0], al[0], bh[0], bl[0]);
        #pragma unroll
        for (int ks = 0; ks < 4; ks++) {
            const int cur = ks & 1, nxt = cur ^ 1;
            if (ks < 3) ldfrags(sb, ks + 1, ah[nxt], al[nxt], bh[nxt], bl[nxt]);
            #pragma unroll
            for (int mt = 0; mt < 2; mt++)
                #pragma unroll
                for (int nt = 0; nt < 4; nt++) {
                    MMA_BF16(acc[mt][nt], ah[cur][mt], bh[cur][nt]);
                    MMA_BF16(acc[mt][nt], ah[cur][mt], bl[cur][nt]);
                    MMA_BF16(acc[mt][nt], al[cur][mt], bh[cur][nt]);
                }
        }
    }

    // ---- epilogue ----
    #pragma unroll
    for (int mt = 0; mt < 2; mt++) {
        #pragma unroll
        for (int nt = 0; nt < 4; nt++) {
            int row = bm + wm + mt*16 + (lane >> 2);
            int col = bn + wn + nt*8 + (lane & 3)*2;
            float b0, b1;
            if (MODE == 0) {
                b0 = (col   < 512) ? bias0[col]   : ((col   < 1024) ? 0.0f : bias1[col - 1024]);
                b1 = (col+1 < 512) ? bias0[col+1] : ((col+1 < 1024) ? 0.0f : bias1[col+1 - 1024]);
            } else {
                b0 = bias0[col]; b1 = bias0[col+1];
            }
            float* p0 = C + (size_t)row * N + col;
            float* p1 = C + (size_t)(row + 8) * N + col;
            p0[0] = acc[mt][nt][0] + b0;  p0[1] = acc[mt][nt][1] + b1;
            p1[0] = acc[mt][nt][2] + b0;  p1[1] = acc[mt][nt][3] + b1;
        }
    }
}

// ---------------------------------------------------------------------------
// Fused window attention per (b,h). Pt aliased over dead qs/ks storage
// (27.1 KB smem), f32x2 FMA, register softmax, swizzled Pt.
// ---------------------------------------------------------------------------
__global__ __launch_bounds__(256) void attn_kernel(const float* __restrict__ qkv,
                                                   const float* __restrict__ mask,
                                                   __nv_bfloat16* __restrict__ aoh,
                                                   __nv_bfloat16* __restrict__ aol)
{
    const int b = blockIdx.x;
    const int h = blockIdx.y;
    const int w = b & (NW - 1);
    const int tid = threadIdx.x;
    const int wid = tid >> 5, lane = tid & 31;

    __shared__ __align__(16) float pool[4608];
    __shared__ __align__(16) float vs[64][32];
    __shared__ float qn[64], kn[64];
    #define QS(n, d) pool[(n)*36 + (d)]
    #define KS(n, d) pool[2304 + (n)*36 + (d)]
    #define PT(m, c) pool[(m)*68 + (c)]

    const float* base = qkv + (size_t)b * NTOK * QKVCOLS + h * HDIM;
    #pragma unroll
    for (int i = 0; i < 8; i++) {
        int n = wid + i * 8;
        const float* r = base + (size_t)n * QKVCOLS;
        QS(n, lane) = r[lane];
        KS(n, lane) = r[512 + lane];
        vs[n][lane] = r[1024 + lane];
    }
    __syncthreads();

    if (tid < 128) {
        int n = tid & 63;
        bool isq = tid < 64;
        const float4* rr = (const float4*)(isq ? &QS(n, 0) : &KS(n, 0));
        float s = 0.0f;
        #pragma unroll
        for (int j = 0; j < 8; j++) {
            float4 v = rr[j];
            s = fmaf(v.x, v.x, s); s = fmaf(v.y, v.y, s);
            s = fmaf(v.z, v.z, s); s = fmaf(v.w, v.w, s);
        }
        float inv = 1.0f / fmaxf(sqrtf(s), 1e-12f);
        if (isq) qn[n] = inv; else kn[n] = inv;
    }

    u64t s01[8];
    #pragma unroll
    for (int r = 0; r < 8; r++) s01[r] = pk2(0.0f, 0.0f);
    #pragma unroll
    for (int d4 = 0; d4 < 32; d4 += 4) {
        float4 kv0 = *(const float4*)&KS(lane, d4);
        float4 kv1 = *(const float4*)&KS(lane + 32, d4);
        u64t kx = pk2(kv0.x, kv1.x);
        u64t ky = pk2(kv0.y, kv1.y);
        u64t kz = pk2(kv0.z, kv1.z);
        u64t kw = pk2(kv0.w, kv1.w);
        #pragma unroll
        for (int r = 0; r < 8; r++) {
            float4 qv = *(const float4*)&QS(wid*8 + r, d4);
            fma2(s01[r], pk2(qv.x, qv.x), kx);
            fma2(s01[r], pk2(qv.y, qv.y), ky);
            fma2(s01[r], pk2(qv.z, qv.z), kz);
            fma2(s01[r], pk2(qv.w, qv.w), kw);
        }
    }
    __syncthreads();

    const float scale = g_scale[h];
    const float kn0 = kn[lane], kn1 = kn[lane + 32];
    const float* rb = g_rel_bias + h * (NTOK * NTOK);
    const float* mk = mask + (size_t)w * (NTOK * NTOK);

    const int swz0 = (lane & 7) << 3;
    const int swz1 = ((lane + 32) & 7) << 3;
    #pragma unroll
    for (int r = 0; r < 8; r++) {
        int n = wid*8 + r;
        float qsc = qn[n] * scale;
        int off = n*64 + lane;
        float2 sv = upk2(s01[r]);
        float x0 = sv.x*qsc*kn0 + rb[off]      + mk[off];
        float x1 = sv.y*qsc*kn1 + rb[off + 32] + mk[off + 32];
        float mx = fmaxf(x0, x1);
        #pragma unroll
        for (int o = 16; o > 0; o >>= 1)
            mx = fmaxf(mx, __shfl_xor_sync(0xffffffffu, mx, o));
        float e0 = __expf(x0 - mx);
        float e1 = __expf(x1 - mx);
        float sm = e0 + e1;
        #pragma unroll
        for (int o = 16; o > 0; o >>= 1)
            sm += __shfl_xor_sync(0xffffffffu, sm, o);
        float inv = 1.0f / sm;
        PT(lane,      n ^ swz0) = e0 * inv;
        PT(lane + 32, n ^ swz1) = e1 * inv;
    }
    __syncthreads();

    u64t o01 = pk2(0.f,0.f), o23 = pk2(0.f,0.f), o45 = pk2(0.f,0.f), o67 = pk2(0.f,0.f);
    #pragma unroll
    for (int m = 0; m < 64; m++) {
        float vm = vs[m][lane];
        u64t vmd = pk2(vm, vm);
        const float* prow = &PT(m, (wid ^ (m & 7)) * 8);
        float4 p0 = *(const float4*)(prow);
        float4 p1 = *(const float4*)(prow + 4);
        fma2(o01, pk2(p0.x, p0.y), vmd);
        fma2(o23, pk2(p0.z, p0.w), vmd);
        fma2(o45, pk2(p1.x, p1.y), vmd);
        fma2(o67, pk2(p1.z, p1.w), vmd);
    }
    float o[8];
    { float2 t = upk2(o01); o[0] = t.x; o[1] = t.y; }
    { float2 t = upk2(o23); o[2] = t.x; o[3] = t.y; }
    { float2 t = upk2(o45); o[4] = t.x; o[5] = t.y; }
    { float2 t = upk2(o67); o[6] = t.x; o[7] = t.y; }

    #pragma unroll
    for (int r = 0; r < 8; r++) {
        size_t oi = (size_t)(b*NTOK + wid*8 + r) * DIM + h*HDIM + lane;
        __nv_bfloat16 hi = __float2bfloat16(o[r]);
        __nv_bfloat16 lo = __float2bfloat16(o[r] - __bfloat162float(hi));
        aoh[oi] = hi;
        aol[oi] = lo;
    }
    #undef QS
    #undef KS
    #undef PT
}

// ---------------------------------------------------------------------------
// Launch order keeps gemm_bf16_128<0> at position #4 (the ncu slot).
// ---------------------------------------------------------------------------
extern "C" void kernel_launch(void* const* d_in, const int* in_sizes, int n_in,
                              void* d_out, int out_size)
{
    const float* x           = (const float*)d_in[0];
    const float* mask        = (const float*)d_in[1];
    const float* qkv_w       = (const float*)d_in[2];
    const float* q_bias      = (const float*)d_in[3];
    const float* v_bias      = (const float*)d_in[4];
    const float* logit_scale = (const float*)d_in[5];
    const float* cpb_w1      = (const float*)d_in[6];
    const float* cpb_b1      = (const float*)d_in[7];
    const float* cpb_w2      = (const float*)d_in[8];
    const float* proj_w      = (const float*)d_in[9];
    const float* proj_b      = (const float*)d_in[10];
    const float* rel_table   = (const float*)d_in[11];
    const int*   rel_idx     = (const int*)d_in[12];
    float*       out         = (float*)d_out;

    float *qkv_ptr;
    __nv_bfloat16 *xh, *xl, *wh, *wl, *ph, *pl, *aoh, *aol;
    cudaGetSymbolAddress((void**)&qkv_ptr, g_qkv);
    cudaGetSymbolAddress((void**)&xh, g_xh);   cudaGetSymbolAddress((void**)&xl, g_xl);
    cudaGetSymbolAddress((void**)&wh, g_wh);   cudaGetSymbolAddress((void**)&wl, g_wl);
    cudaGetSymbolAddress((void**)&ph, g_ph);   cudaGetSymbolAddress((void**)&pl, g_pl);
    cudaGetSymbolAddress((void**)&aoh, g_aoh); cudaGetSymbolAddress((void**)&aol, g_aol);

    cudaFuncSetAttribute(gemm_bf16_128<0>, cudaFuncAttributeMaxDynamicSharedMemorySize, GEMM_SMEM);
    cudaFuncSetAttribute(gemm_bf16_128<1>, cudaFuncAttributeMaxDynamicSharedMemorySize, GEMM_SMEM);

    // 1-3: splits
    split_f32<<<(ROWS*DIM/4 + 255)/256, 256>>>(x, xh, xl, ROWS*DIM/4);
    split_f32<<<(QKVCOLS*DIM/4 + 255)/256, 256>>>(qkv_w, wh, wl, QKVCOLS*DIM/4);
    split_f32<<<(DIM*DIM/4 + 255)/256, 256>>>(proj_w, ph, pl, DIM*DIM/4);

    // 4: QKV GEMM  <-- profiled slot
    gemm_bf16_128<0><<<dim3(QKVCOLS/128, ROWS/128), 512, GEMM_SMEM>>>(
        xh, xl, wh, wl, q_bias, v_bias, qkv_ptr, QKVCOLS);

    // 5-6: CPB
    cpb_mlp_kernel<<<225, 512>>>(rel_table, cpb_w1, cpb_b1, cpb_w2);
    cpb_expand_kernel<<<256, 256>>>(rel_idx, logit_scale);

    // 7: attention
    attn_kernel<<<dim3(BATCH, HEADS), 256>>>(qkv_ptr, mask, aoh, aol);

    // 8: proj GEMM
    gemm_bf16_128<1><<<dim3(DIM/128, ROWS/128), 512, GEMM_SMEM>>>(
        aoh, aol, ph, pl, proj_b, nullptr, out, DIM);
}

// round 14
// speedup vs baseline: 1.0455x; 1.0455x over previous
#include <cuda_runtime.h>
#include <cuda_bf16.h>
#include <math.h>
#include <stdint.h>

#define BATCH   1024
#define NTOK    64
#define DIM     512
#define HEADS   16
#define HDIM    32
#define NW      64
#define ROWS    (BATCH * NTOK)      // 65536
#define QKVCOLS (3 * DIM)           // 1536

// ---------------- device scratch ----------------
__device__ __align__(16) float         g_qkv[(size_t)ROWS * QKVCOLS];
__device__ __align__(16) __nv_bfloat16 g_xh[(size_t)ROWS * DIM];
__device__ __align__(16) __nv_bfloat16 g_xl[(size_t)ROWS * DIM];
__device__ __align__(16) __nv_bfloat16 g_wh[(size_t)QKVCOLS * DIM];
__device__ __align__(16) __nv_bfloat16 g_wl[(size_t)QKVCOLS * DIM];
__device__ __align__(16) __nv_bfloat16 g_ph[(size_t)DIM * DIM];
__device__ __align__(16) __nv_bfloat16 g_pl[(size_t)DIM * DIM];
__device__ __align__(16) __nv_bfloat16 g_aoh[(size_t)ROWS * DIM];
__device__ __align__(16) __nv_bfloat16 g_aol[(size_t)ROWS * DIM];
__device__ float g_bias_table[225 * HEADS];
__device__ float g_rel_bias[HEADS * NTOK * NTOK];
__device__ float g_scale[HEADS];

// ---------------- helpers ----------------
__device__ __forceinline__ uint32_t smem_u32(const void* p) {
    uint32_t a;
    asm("{ .reg .u64 t; cvta.to.shared.u64 t, %1; cvt.u32.u64 %0, t; }" : "=r"(a) : "l"(p));
    return a;
}

#define LDSM4(r0,r1,r2,r3, addr) \
    asm volatile("ldmatrix.sync.aligned.m8n8.x4.shared.b16 {%0,%1,%2,%3}, [%4];" \
        : "=r"(r0),"=r"(r1),"=r"(r2),"=r"(r3) : "r"(addr))

#define MMA_BF16(d, a, b) \
    asm volatile("mma.sync.aligned.m16n8k16.row.col.f32.bf16.bf16.f32 " \
        "{%0,%1,%2,%3}, {%4,%5,%6,%7}, {%8,%9}, {%0,%1,%2,%3};" \
        : "+f"(d[0]),"+f"(d[1]),"+f"(d[2]),"+f"(d[3]) \
        : "r"(a[0]),"r"(a[1]),"r"(a[2]),"r"(a[3]),"r"(b[0]),"r"(b[1]))

#define CP16(dst, src) \
    asm volatile("cp.async.ca.shared.global [%0], [%1], 16;" :: "r"(dst), "l"(src))
#define CP_COMMIT() asm volatile("cp.async.commit_group;" ::: "memory")
#define CP_WAIT0()  asm volatile("cp.async.wait_group 0;" ::: "memory")

// ---- packed f32x2 (FFMA2) ----
typedef unsigned long long u64t;
__device__ __forceinline__ u64t pk2(float lo, float hi) {
    u64t r; asm("mov.b64 %0, {%1, %2};" : "=l"(r) : "f"(lo), "f"(hi)); return r;
}
__device__ __forceinline__ void fma2(u64t& d, u64t a, u64t b) {
    asm("fma.rn.f32x2 %0, %1, %2, %0;" : "+l"(d) : "l"(a), "l"(b));
}
__device__ __forceinline__ float2 upk2(u64t v) {
    float2 r; asm("mov.b64 {%0, %1}, %2;" : "=f"(r.x), "=f"(r.y) : "l"(v)); return r;
}

// ---------------- fp32 -> bf16 hi/lo split ----------------
__global__ void split_f32(const float* __restrict__ in,
                          __nv_bfloat16* __restrict__ hi,
                          __nv_bfloat16* __restrict__ lo, int n4)
{
    int i = blockIdx.x * blockDim.x + threadIdx.x;
    if (i >= n4) return;
    float4 v = ((const float4*)in)[i];
    __nv_bfloat16 h[4], l[4];
    float x[4] = {v.x, v.y, v.z, v.w};
    #pragma unroll
    for (int j = 0; j < 4; j++) {
        h[j] = __float2bfloat16(x[j]);
        l[j] = __float2bfloat16(x[j] - __bfloat162float(h[j]));
    }
    ((uint2*)hi)[i] = *(uint2*)h;
    ((uint2*)lo)[i] = *(uint2*)l;
}

// ---------------- CPB MLP ----------------
__global__ void cpb_mlp_kernel(const float* __restrict__ tbl,
                               const float* __restrict__ w1,
                               const float* __restrict__ b1,
                               const float* __restrict__ w2)
{
    int i = blockIdx.x, j = threadIdx.x;
    __shared__ float hid[512];
    float hv = tbl[i*2+0] * w1[j*2+0] + tbl[i*2+1] * w1[j*2+1] + b1[j];
    hid[j] = fmaxf(hv, 0.0f);
    __syncthreads();
    int warp = j >> 5, lane = j & 31;
    float s = 0.0f;
    #pragma unroll
    for (int c = lane; c < 512; c += 32) s += hid[c] * w2[warp*512 + c];
    #pragma unroll
    for (int off = 16; off > 0; off >>= 1) s += __shfl_xor_sync(0xffffffffu, s, off);
    if (lane == 0) g_bias_table[i*HEADS + warp] = s;
}

__global__ void cpb_expand_kernel(const int* __restrict__ idx,
                                  const float* __restrict__ logit_scale)
{
    int g = blockIdx.x * 256 + threadIdx.x;
    int h = g >> 12, nm = g & 4095;
    float v = g_bias_table[idx[nm]*HEADS + h];
    g_rel_bias[g] = 16.0f / (1.0f + expf(-v));
    if (g < HEADS) g_scale[g] = expf(fminf(logit_scale[g], 4.60517018598809136804f));
}

// ---------------------------------------------------------------------------
// split-bf16 GEMM (NT): C[M,N] = (Ah+Al)[M,K] @ (Bh+Bl)[N,K]^T + bias
// BM=BN=128, BK=32, K=512. 512 thr = 16 warps (4m x 4n), warp 32x32.
// 2-stage cp.async pipeline (81.9 KB smem -> 2 CTAs/SM; cross-CTA overlap
// fills barrier/LDSM bubbles in the tensor pipe). R12-proven inner loop.
// ---------------------------------------------------------------------------
#define AB_SZ 10240
#define STG (4 * AB_SZ)          // 40960
#define GEMM_SMEM (2 * STG)      // 81920

template <int MODE>   // 0: qkv bias (q|0|v), 1: proj bias
__global__ __launch_bounds__(512, 2) void gemm_bf16_128(
    const __nv_bfloat16* __restrict__ Ah, const __nv_bfloat16* __restrict__ Al,
    const __nv_bfloat16* __restrict__ Bh, const __nv_bfloat16* __restrict__ Bl,
    const float* __restrict__ bias0, const float* __restrict__ bias1,
    float* __restrict__ C, int N)
{
    extern __shared__ char smem[];

    const int tid  = threadIdx.x;
    const int bm   = blockIdx.y * 128;
    const int bn   = blockIdx.x * 128;
    const int wid  = tid >> 5, lane = tid & 31;
    const int wm   = (wid & 3) * 32;
    const int wn   = (wid >> 2) * 32;

    const uint32_t sbase = smem_u32(smem);

    float acc[2][4][4];
    #pragma unroll
    for (int a = 0; a < 2; a++)
        #pragma unroll
        for (int b = 0; b < 4; b++)
            #pragma unroll
            for (int c = 0; c < 4; c++) acc[a][b][c] = 0.0f;

    const int lrow = tid >> 2;       // 0..127
    const int lq   = tid & 3;        // 0..3
    auto load_stage = [&](int kt, int buf) {
        const uint32_t sb = sbase + buf * STG;
        const size_t goff_a = (size_t)(bm + lrow) * 512 + kt * 32 + lq * 8;
        const size_t goff_b = (size_t)(bn + lrow) * 512 + kt * 32 + lq * 8;
        const uint32_t d = sb + (uint32_t)(lrow * 80 + lq * 16);
        CP16(d,             (const char*)Ah + goff_a * 2);
        CP16(d +   AB_SZ,   (const char*)Al + goff_a * 2);
        CP16(d + 2*AB_SZ,   (const char*)Bh + goff_b * 2);
        CP16(d + 3*AB_SZ,   (const char*)Bl + goff_b * 2);
        CP_COMMIT();
    };

    load_stage(0, 0);

    for (int kt = 0; kt < 16; kt++) {
        const int buf = kt & 1;
        CP_WAIT0();            // stage kt landed
        __syncthreads();       // visible to all; prior compute (kt-1) done
        if (kt + 1 < 16) load_stage(kt + 1, buf ^ 1);   // overlaps compute kt

        const uint32_t sb  = sbase + buf * STG;
        const uint32_t aAh = sb;
        const uint32_t aAl = sb +   AB_SZ;
        const uint32_t aBh = sb + 2*AB_SZ;
        const uint32_t aBl = sb + 3*AB_SZ;

        #pragma unroll
        for (int ks = 0; ks < 2; ks++) {
            const int kb = ks * 16;
            uint32_t ah[2][4], al[2][4], bh[4][2], bl[4][2];
            #pragma unroll
            for (int mt = 0; mt < 2; mt++) {
                int row = wm + mt*16 + (lane & 15);
                int col = kb + (lane >> 4) * 8;
                uint32_t off = (uint32_t)(row*80 + col*2);
                LDSM4(ah[mt][0], ah[mt][1], ah[mt][2], ah[mt][3], aAh + off);
                LDSM4(al[mt][0], al[mt][1], al[mt][2], al[mt][3], aAl + off);
            }
            #pragma unroll
            for (int np = 0; np < 2; np++) {
                int g = lane >> 3;
                int row = wn + np*16 + (lane & 7) + ((g >> 1) & 1) * 8;
                int col = kb + (g & 1) * 8;
                uint32_t off = (uint32_t)(row*80 + col*2);
                LDSM4(bh[2*np][0], bh[2*np][1], bh[2*np+1][0], bh[2*np+1][1], aBh + off);
                LDSM4(bl[2*np][0], bl[2*np][1], bl[2*np+1][0], bl[2*np+1][1], aBl + off);
            }
            #pragma unroll
            for (int mt = 0; mt < 2; mt++)
                #pragma unroll
                for (int nt = 0; nt < 4; nt++) {
                    MMA_BF16(acc[mt][nt], ah[mt], bh[nt]);
                    MMA_BF16(acc[mt][nt], ah[mt], bl[nt]);
                    MMA_BF16(acc[mt][nt], al[mt], bh[nt]);
                }
        }
        __syncthreads();   // compute kt done -> buf may be overwritten next iter
    }

    #pragma unroll
    for (int mt = 0; mt < 2; mt++) {
        #pragma unroll
        for (int nt = 0; nt < 4; nt++) {
            int row = bm + wm + mt*16 + (lane >> 2);
            int col = bn + wn + nt*8 + (lane & 3)*2;
            float b0, b1;
            if (MODE == 0) {
                b0 = (col   < 512) ? bias0[col]   : ((col   < 1024) ? 0.0f : bias1[col - 1024]);
                b1 = (col+1 < 512) ? bias0[col+1] : ((col+1 < 1024) ? 0.0f : bias1[col+1 - 1024]);
            } else {
                b0 = bias0[col]; b1 = bias0[col+1];
            }
            float* p0 = C + (size_t)row * N + col;
            float* p1 = C + (size_t)(row + 8) * N + col;
            p0[0] = acc[mt][nt][0] + b0;  p0[1] = acc[mt][nt][1] + b1;
            p1[0] = acc[mt][nt][2] + b0;  p1[1] = acc[mt][nt][3] + b1;
        }
    }
}

// ---------------------------------------------------------------------------
// Fused window attention per (b,h). Pt aliased over dead qs/ks storage
// (27.1 KB smem), f32x2 FMA, register softmax, swizzled Pt.
// ---------------------------------------------------------------------------
__global__ __launch_bounds__(256) void attn_kernel(const float* __restrict__ qkv,
                                                   const float* __restrict__ mask,
                                                   __nv_bfloat16* __restrict__ aoh,
                                                   __nv_bfloat16* __restrict__ aol)
{
    const int b = blockIdx.x;
    const int h = blockIdx.y;
    const int w = b & (NW - 1);
    const int tid = threadIdx.x;
    const int wid = tid >> 5, lane = tid & 31;

    __shared__ __align__(16) float pool[4608];
    __shared__ __align__(16) float vs[64][32];
    __shared__ float qn[64], kn[64];
    #define QS(n, d) pool[(n)*36 + (d)]
    #define KS(n, d) pool[2304 + (n)*36 + (d)]
    #define PT(m, c) pool[(m)*68 + (c)]

    const float* base = qkv + (size_t)b * NTOK * QKVCOLS + h * HDIM;
    #pragma unroll
    for (int i = 0; i < 8; i++) {
        int n = wid + i * 8;
        const float* r = base + (size_t)n * QKVCOLS;
        QS(n, lane) = r[lane];
        KS(n, lane) = r[512 + lane];
        vs[n][lane] = r[1024 + lane];
    }
    __syncthreads();

    if (tid < 128) {
        int n = tid & 63;
        bool isq = tid < 64;
        const float4* rr = (const float4*)(isq ? &QS(n, 0) : &KS(n, 0));
        float s = 0.0f;
        #pragma unroll
        for (int j = 0; j < 8; j++) {
            float4 v = rr[j];
            s = fmaf(v.x, v.x, s); s = fmaf(v.y, v.y, s);
            s = fmaf(v.z, v.z, s); s = fmaf(v.w, v.w, s);
        }
        float inv = 1.0f / fmaxf(sqrtf(s), 1e-12f);
        if (isq) qn[n] = inv; else kn[n] = inv;
    }

    u64t s01[8];
    #pragma unroll
    for (int r = 0; r < 8; r++) s01[r] = pk2(0.0f, 0.0f);
    #pragma unroll
    for (int d4 = 0; d4 < 32; d4 += 4) {
        float4 kv0 = *(const float4*)&KS(lane, d4);
        float4 kv1 = *(const float4*)&KS(lane + 32, d4);
        u64t kx = pk2(kv0.x, kv1.x);
        u64t ky = pk2(kv0.y, kv1.y);
        u64t kz = pk2(kv0.z, kv1.z);
        u64t kw = pk2(kv0.w, kv1.w);
        #pragma unroll
        for (int r = 0; r < 8; r++) {
            float4 qv = *(const float4*)&QS(wid*8 + r, d4);
            fma2(s01[r], pk2(qv.x, qv.x), kx);
            fma2(s01[r], pk2(qv.y, qv.y), ky);
            fma2(s01[r], pk2(qv.z, qv.z), kz);
            fma2(s01[r], pk2(qv.w, qv.w), kw);
        }
    }
    __syncthreads();

    const float scale = g_scale[h];
    const float kn0 = kn[lane], kn1 = kn[lane + 32];
    const float* rb = g_rel_bias + h * (NTOK * NTOK);
    const float* mk = mask + (size_t)w * (NTOK * NTOK);

    const int swz0 = (lane & 7) << 3;
    const int swz1 = ((lane + 32) & 7) << 3;
    #pragma unroll
    for (int r = 0; r < 8; r++) {
        int n = wid*8 + r;
        float qsc = qn[n] * scale;
        int off = n*64 + lane;
        float2 sv = upk2(s01[r]);
        float x0 = sv.x*qsc*kn0 + rb[off]      + mk[off];
        float x1 = sv.y*qsc*kn1 + rb[off + 32] + mk[off + 32];
        float mx = fmaxf(x0, x1);
        #pragma unroll
        for (int o = 16; o > 0; o >>= 1)
            mx = fmaxf(mx, __shfl_xor_sync(0xffffffffu, mx, o));
        float e0 = __expf(x0 - mx);
        float e1 = __expf(x1 - mx);
        float sm = e0 + e1;
        #pragma unroll
        for (int o = 16; o > 0; o >>= 1)
            sm += __shfl_xor_sync(0xffffffffu, sm, o);
        float inv = 1.0f / sm;
        PT(lane,      n ^ swz0) = e0 * inv;
        PT(lane + 32, n ^ swz1) = e1 * inv;
    }
    __syncthreads();

    u64t o01 = pk2(0.f,0.f), o23 = pk2(0.f,0.f), o45 = pk2(0.f,0.f), o67 = pk2(0.f,0.f);
    #pragma unroll
    for (int m = 0; m < 64; m++) {
        float vm = vs[m][lane];
        u64t vmd = pk2(vm, vm);
        const float* prow = &PT(m, (wid ^ (m & 7)) * 8);
        float4 p0 = *(const float4*)(prow);
        float4 p1 = *(const float4*)(prow + 4);
        fma2(o01, pk2(p0.x, p0.y), vmd);
        fma2(o23, pk2(p0.z, p0.w), vmd);
        fma2(o45, pk2(p1.x, p1.y), vmd);
        fma2(o67, pk2(p1.z, p1.w), vmd);
    }
    float o[8];
    { float2 t = upk2(o01); o[0] = t.x; o[1] = t.y; }
    { float2 t = upk2(o23); o[2] = t.x; o[3] = t.y; }
    { float2 t = upk2(o45); o[4] = t.x; o[5] = t.y; }
    { float2 t = upk2(o67); o[6] = t.x; o[7] = t.y; }

    #pragma unroll
    for (int r = 0; r < 8; r++) {
        size_t oi = (size_t)(b*NTOK + wid*8 + r) * DIM + h*HDIM + lane;
        __nv_bfloat16 hi = __float2bfloat16(o[r]);
        __nv_bfloat16 lo = __float2bfloat16(o[r] - __bfloat162float(hi));
        aoh[oi] = hi;
        aol[oi] = lo;
    }
    #undef QS
    #undef KS
    #undef PT
}

// ---------------------------------------------------------------------------
// Launch order keeps gemm_bf16_128<0> at position #4 (the ncu slot).
// ---------------------------------------------------------------------------
extern "C" void kernel_launch(void* const* d_in, const int* in_sizes, int n_in,
                              void* d_out, int out_size)
{
    const float* x           = (const float*)d_in[0];
    const float* mask        = (const float*)d_in[1];
    const float* qkv_w       = (const float*)d_in[2];
    const float* q_bias      = (const float*)d_in[3];
    const float* v_bias      = (const float*)d_in[4];
    const float* logit_scale = (const float*)d_in[5];
    const float* cpb_w1      = (const float*)d_in[6];
    const float* cpb_b1      = (const float*)d_in[7];
    const float* cpb_w2      = (const float*)d_in[8];
    const float* proj_w      = (const float*)d_in[9];
    const float* proj_b      = (const float*)d_in[10];
    const float* rel_table   = (const float*)d_in[11];
    const int*   rel_idx     = (const int*)d_in[12];
    float*       out         = (float*)d_out;

    float *qkv_ptr;
    __nv_bfloat16 *xh, *xl, *wh, *wl, *ph, *pl, *aoh, *aol;
    cudaGetSymbolAddress((void**)&qkv_ptr, g_qkv);
    cudaGetSymbolAddress((void**)&xh, g_xh);   cudaGetSymbolAddress((void**)&xl, g_xl);
    cudaGetSymbolAddress((void**)&wh, g_wh);   cudaGetSymbolAddress((void**)&wl, g_wl);
    cudaGetSymbolAddress((void**)&ph, g_ph);   cudaGetSymbolAddress((void**)&pl, g_pl);
    cudaGetSymbolAddress((void**)&aoh, g_aoh); cudaGetSymbolAddress((void**)&aol, g_aol);

    cudaFuncSetAttribute(gemm_bf16_128<0>, cudaFuncAttributeMaxDynamicSharedMemorySize, GEMM_SMEM);
    cudaFuncSetAttribute(gemm_bf16_128<1>, cudaFuncAttributeMaxDynamicSharedMemorySize, GEMM_SMEM);

    // 1-3: splits
    split_f32<<<(ROWS*DIM/4 + 255)/256, 256>>>(x, xh, xl, ROWS*DIM/4);
    split_f32<<<(QKVCOLS*DIM/4 + 255)/256, 256>>>(qkv_w, wh, wl, QKVCOLS*DIM/4);
    split_f32<<<(DIM*DIM/4 + 255)/256, 256>>>(proj_w, ph, pl, DIM*DIM/4);

    // 4: QKV GEMM  <-- profiled slot
    gemm_bf16_128<0><<<dim3(QKVCOLS/128, ROWS/128), 512, GEMM_SMEM>>>(
        xh, xl, wh, wl, q_bias, v_bias, qkv_ptr, QKVCOLS);

    // 5-6: CPB
    cpb_mlp_kernel<<<225, 512>>>(rel_table, cpb_w1, cpb_b1, cpb_w2);
    cpb_expand_kernel<<<256, 256>>>(rel_idx, logit_scale);

    // 7: attention
    attn_kernel<<<dim3(BATCH, HEADS), 256>>>(qkv_ptr, mask, aoh, aol);

    // 8: proj GEMM
    gemm_bf16_128<1><<<dim3(DIM/128, ROWS/128), 512, GEMM_SMEM>>>(
        aoh, aol, ph, pl, proj_b, nullptr, out, DIM);
}

// round 15
// speedup vs baseline: 1.1707x; 1.1198x over previous
#include <cuda_runtime.h>
#include <cuda_bf16.h>
#include <math.h>
#include <stdint.h>

#define BATCH   1024
#define NTOK    64
#define DIM     512
#define HEADS   16
#define HDIM    32
#define NW      64
#define ROWS    (BATCH * NTOK)      // 65536
#define QKVCOLS (3 * DIM)           // 1536

// ---------------- device scratch ----------------
__device__ __align__(16) float         g_qkv[(size_t)ROWS * QKVCOLS];
__device__ __align__(16) __nv_bfloat16 g_xh[(size_t)ROWS * DIM];
__device__ __align__(16) __nv_bfloat16 g_xl[(size_t)ROWS * DIM];
__device__ __align__(16) __nv_bfloat16 g_wh[(size_t)QKVCOLS * DIM];
__device__ __align__(16) __nv_bfloat16 g_wl[(size_t)QKVCOLS * DIM];
__device__ __align__(16) __nv_bfloat16 g_ph[(size_t)DIM * DIM];
__device__ __align__(16) __nv_bfloat16 g_pl[(size_t)DIM * DIM];
__device__ __align__(16) __nv_bfloat16 g_aoh[(size_t)ROWS * DIM];
__device__ __align__(16) __nv_bfloat16 g_aol[(size_t)ROWS * DIM];
__device__ float g_bias_table[225 * HEADS];
__device__ float g_rel_bias[HEADS * NTOK * NTOK];
__device__ float g_scale[HEADS];

// ---------------- helpers ----------------
__device__ __forceinline__ uint32_t smem_u32(const void* p) {
    uint32_t a;
    asm("{ .reg .u64 t; cvta.to.shared.u64 t, %1; cvt.u32.u64 %0, t; }" : "=r"(a) : "l"(p));
    return a;
}

#define LDSM4(r0,r1,r2,r3, addr) \
    asm volatile("ldmatrix.sync.aligned.m8n8.x4.shared.b16 {%0,%1,%2,%3}, [%4];" \
        : "=r"(r0),"=r"(r1),"=r"(r2),"=r"(r3) : "r"(addr))

#define MMA_BF16(d, a, b) \
    asm volatile("mma.sync.aligned.m16n8k16.row.col.f32.bf16.bf16.f32 " \
        "{%0,%1,%2,%3}, {%4,%5,%6,%7}, {%8,%9}, {%0,%1,%2,%3};" \
        : "+f"(d[0]),"+f"(d[1]),"+f"(d[2]),"+f"(d[3]) \
        : "r"(a[0]),"r"(a[1]),"r"(a[2]),"r"(a[3]),"r"(b[0]),"r"(b[1]))

#define CP16(dst, src) \
    asm volatile("cp.async.ca.shared.global [%0], [%1], 16;" :: "r"(dst), "l"(src))
#define CP_COMMIT() asm volatile("cp.async.commit_group;" ::: "memory")
#define CP_WAIT1()  asm volatile("cp.async.wait_group 1;" ::: "memory")

// ---- packed f32x2 (FFMA2) ----
typedef unsigned long long u64t;
__device__ __forceinline__ u64t pk2(float lo, float hi) {
    u64t r; asm("mov.b64 %0, {%1, %2};" : "=l"(r) : "f"(lo), "f"(hi)); return r;
}
__device__ __forceinline__ void fma2(u64t& d, u64t a, u64t b) {
    asm("fma.rn.f32x2 %0, %1, %2, %0;" : "+l"(d) : "l"(a), "l"(b));
}
__device__ __forceinline__ float2 upk2(u64t v) {
    float2 r; asm("mov.b64 {%0, %1}, %2;" : "=f"(r.x), "=f"(r.y) : "l"(v)); return r;
}

// ---------------- fp32 -> bf16 hi/lo split ----------------
__global__ void split_f32(const float* __restrict__ in,
                          __nv_bfloat16* __restrict__ hi,
                          __nv_bfloat16* __restrict__ lo, int n4)
{
    int i = blockIdx.x * blockDim.x + threadIdx.x;
    if (i >= n4) return;
    float4 v = ((const float4*)in)[i];
    __nv_bfloat16 h[4], l[4];
    float x[4] = {v.x, v.y, v.z, v.w};
    #pragma unroll
    for (int j = 0; j < 4; j++) {
        h[j] = __float2bfloat16(x[j]);
        l[j] = __float2bfloat16(x[j] - __bfloat162float(h[j]));
    }
    ((uint2*)hi)[i] = *(uint2*)h;
    ((uint2*)lo)[i] = *(uint2*)l;
}

// ---------------- CPB MLP ----------------
__global__ void cpb_mlp_kernel(const float* __restrict__ tbl,
                               const float* __restrict__ w1,
                               const float* __restrict__ b1,
                               const float* __restrict__ w2)
{
    int i = blockIdx.x, j = threadIdx.x;
    __shared__ float hid[512];
    float hv = tbl[i*2+0] * w1[j*2+0] + tbl[i*2+1] * w1[j*2+1] + b1[j];
    hid[j] = fmaxf(hv, 0.0f);
    __syncthreads();
    int warp = j >> 5, lane = j & 31;
    float s = 0.0f;
    #pragma unroll
    for (int c = lane; c < 512; c += 32) s += hid[c] * w2[warp*512 + c];
    #pragma unroll
    for (int off = 16; off > 0; off >>= 1) s += __shfl_xor_sync(0xffffffffu, s, off);
    if (lane == 0) g_bias_table[i*HEADS + warp] = s;
}

__global__ void cpb_expand_kernel(const int* __restrict__ idx,
                                  const float* __restrict__ logit_scale)
{
    int g = blockIdx.x * 256 + threadIdx.x;
    int h = g >> 12, nm = g & 4095;
    float v = g_bias_table[idx[nm]*HEADS + h];
    g_rel_bias[g] = 16.0f / (1.0f + expf(-v));
    if (g < HEADS) g_scale[g] = expf(fminf(logit_scale[g], 4.60517018598809136804f));
}

// ---------------------------------------------------------------------------
// split-bf16 GEMM (NT): C[M,N] = (Ah+Al)[M,K] @ (Bh+Bl)[N,K]^T + bias
// BM=BN=128, BK=32, K=512. 512 thr = 16 warps (4m x 4n), warp 32x32.
// 3-stage cp.async pipeline, ONE barrier per k-iter (R12-proven).
// NEW: warp-parity ks skew — odd warps process ks groups in order (1,0) so
// half the warps LDSM while half MMA, interleaving LDS and tensor pipes.
// ---------------------------------------------------------------------------
#define AB_SZ 10240
#define STG (4 * AB_SZ)          // 40960
#define GEMM_SMEM (3 * STG)      // 122880

template <int MODE>   // 0: qkv bias (q|0|v), 1: proj bias
__global__ __launch_bounds__(512, 1) void gemm_bf16_128(
    const __nv_bfloat16* __restrict__ Ah, const __nv_bfloat16* __restrict__ Al,
    const __nv_bfloat16* __restrict__ Bh, const __nv_bfloat16* __restrict__ Bl,
    const float* __restrict__ bias0, const float* __restrict__ bias1,
    float* __restrict__ C, int N)
{
    extern __shared__ char smem[];

    const int tid  = threadIdx.x;
    const int bm   = blockIdx.y * 128;
    const int bn   = blockIdx.x * 128;
    const int wid  = tid >> 5, lane = tid & 31;
    const int wm   = (wid & 3) * 32;
    const int wn   = (wid >> 2) * 32;
    const int ks0  = wid & 1;        // ks processing order skew per warp parity

    const uint32_t sbase = smem_u32(smem);

    float acc[2][4][4];
    #pragma unroll
    for (int a = 0; a < 2; a++)
        #pragma unroll
        for (int b = 0; b < 4; b++)
            #pragma unroll
            for (int c = 0; c < 4; c++) acc[a][b][c] = 0.0f;

    const int lrow = tid >> 2;       // 0..127
    const int lq   = tid & 3;        // 0..3
    auto load_stage = [&](int kt, int buf) {
        const uint32_t sb = sbase + buf * STG;
        const size_t goff_a = (size_t)(bm + lrow) * 512 + kt * 32 + lq * 8;
        const size_t goff_b = (size_t)(bn + lrow) * 512 + kt * 32 + lq * 8;
        const uint32_t d = sb + (uint32_t)(lrow * 80 + lq * 16);
        CP16(d,             (const char*)Ah + goff_a * 2);
        CP16(d +   AB_SZ,   (const char*)Al + goff_a * 2);
        CP16(d + 2*AB_SZ,   (const char*)Bh + goff_b * 2);
        CP16(d + 3*AB_SZ,   (const char*)Bl + goff_b * 2);
        CP_COMMIT();
    };

    load_stage(0, 0);
    load_stage(1, 1);

    for (int kt = 0; kt < 16; kt++) {
        const int buf = kt % 3;
        CP_WAIT1();
        __syncthreads();   // stage kt visible; compute kt-1 done -> its buf free

        if (kt + 2 < 16) load_stage(kt + 2, (kt + 2) % 3);
        else CP_COMMIT();

        const uint32_t sb  = sbase + buf * STG;
        const uint32_t aAh = sb;
        const uint32_t aAl = sb +   AB_SZ;
        const uint32_t aBh = sb + 2*AB_SZ;
        const uint32_t aBl = sb + 3*AB_SZ;

        #pragma unroll
        for (int i = 0; i < 2; i++) {
            const int ks = ks0 ^ i;          // even warps: 0,1; odd warps: 1,0
            const int kb = ks * 16;
            uint32_t ah[2][4], al[2][4], bh[4][2], bl[4][2];
            #pragma unroll
            for (int mt = 0; mt < 2; mt++) {
                int row = wm + mt*16 + (lane & 15);
                int col = kb + (lane >> 4) * 8;
                uint32_t off = (uint32_t)(row*80 + col*2);
                LDSM4(ah[mt][0], ah[mt][1], ah[mt][2], ah[mt][3], aAh + off);
                LDSM4(al[mt][0], al[mt][1], al[mt][2], al[mt][3], aAl + off);
            }
            #pragma unroll
            for (int np = 0; np < 2; np++) {
                int g = lane >> 3;
                int row = wn + np*16 + (lane & 7) + ((g >> 1) & 1) * 8;
                int col = kb + (g & 1) * 8;
                uint32_t off = (uint32_t)(row*80 + col*2);
                LDSM4(bh[2*np][0], bh[2*np][1], bh[2*np+1][0], bh[2*np+1][1], aBh + off);
                LDSM4(bl[2*np][0], bl[2*np][1], bl[2*np+1][0], bl[2*np+1][1], aBl + off);
            }
            #pragma unroll
            for (int mt = 0; mt < 2; mt++)
                #pragma unroll
                for (int nt = 0; nt < 4; nt++) {
                    MMA_BF16(acc[mt][nt], ah[mt], bh[nt]);
                    MMA_BF16(acc[mt][nt], ah[mt], bl[nt]);
                    MMA_BF16(acc[mt][nt], al[mt], bh[nt]);
                }
        }
    }

    #pragma unroll
    for (int mt = 0; mt < 2; mt++) {
        #pragma unroll
        for (int nt = 0; nt < 4; nt++) {
            int row = bm + wm + mt*16 + (lane >> 2);
            int col = bn + wn + nt*8 + (lane & 3)*2;
            float b0, b1;
            if (MODE == 0) {
                b0 = (col   < 512) ? bias0[col]   : ((col   < 1024) ? 0.0f : bias1[col - 1024]);
                b1 = (col+1 < 512) ? bias0[col+1] : ((col+1 < 1024) ? 0.0f : bias1[col+1 - 1024]);
            } else {
                b0 = bias0[col]; b1 = bias0[col+1];
            }
            float* p0 = C + (size_t)row * N + col;
            float* p1 = C + (size_t)(row + 8) * N + col;
            p0[0] = acc[mt][nt][0] + b0;  p0[1] = acc[mt][nt][1] + b1;
            p1[0] = acc[mt][nt][2] + b0;  p1[1] = acc[mt][nt][3] + b1;
        }
    }
}

// ---------------------------------------------------------------------------
// Fused window attention per (b,h). Pt aliased over dead qs/ks storage
// (27.1 KB smem), f32x2 FMA, register softmax, swizzled Pt.
// ---------------------------------------------------------------------------
__global__ __launch_bounds__(256) void attn_kernel(const float* __restrict__ qkv,
                                                   const float* __restrict__ mask,
                                                   __nv_bfloat16* __restrict__ aoh,
                                                   __nv_bfloat16* __restrict__ aol)
{
    const int b = blockIdx.x;
    const int h = blockIdx.y;
    const int w = b & (NW - 1);
    const int tid = threadIdx.x;
    const int wid = tid >> 5, lane = tid & 31;

    __shared__ __align__(16) float pool[4608];
    __shared__ __align__(16) float vs[64][32];
    __shared__ float qn[64], kn[64];
    #define QS(n, d) pool[(n)*36 + (d)]
    #define KS(n, d) pool[2304 + (n)*36 + (d)]
    #define PT(m, c) pool[(m)*68 + (c)]

    const float* base = qkv + (size_t)b * NTOK * QKVCOLS + h * HDIM;
    #pragma unroll
    for (int i = 0; i < 8; i++) {
        int n = wid + i * 8;
        const float* r = base + (size_t)n * QKVCOLS;
        QS(n, lane) = r[lane];
        KS(n, lane) = r[512 + lane];
        vs[n][lane] = r[1024 + lane];
    }
    __syncthreads();

    if (tid < 128) {
        int n = tid & 63;
        bool isq = tid < 64;
        const float4* rr = (const float4*)(isq ? &QS(n, 0) : &KS(n, 0));
        float s = 0.0f;
        #pragma unroll
        for (int j = 0; j < 8; j++) {
            float4 v = rr[j];
            s = fmaf(v.x, v.x, s); s = fmaf(v.y, v.y, s);
            s = fmaf(v.z, v.z, s); s = fmaf(v.w, v.w, s);
        }
        float inv = 1.0f / fmaxf(sqrtf(s), 1e-12f);
        if (isq) qn[n] = inv; else kn[n] = inv;
    }

    u64t s01[8];
    #pragma unroll
    for (int r = 0; r < 8; r++) s01[r] = pk2(0.0f, 0.0f);
    #pragma unroll
    for (int d4 = 0; d4 < 32; d4 += 4) {
        float4 kv0 = *(const float4*)&KS(lane, d4);
        float4 kv1 = *(const float4*)&KS(lane + 32, d4);
        u64t kx = pk2(kv0.x, kv1.x);
        u64t ky = pk2(kv0.y, kv1.y);
        u64t kz = pk2(kv0.z, kv1.z);
        u64t kw = pk2(kv0.w, kv1.w);
        #pragma unroll
        for (int r = 0; r < 8; r++) {
            float4 qv = *(const float4*)&QS(wid*8 + r, d4);
            fma2(s01[r], pk2(qv.x, qv.x), kx);
            fma2(s01[r], pk2(qv.y, qv.y), ky);
            fma2(s01[r], pk2(qv.z, qv.z), kz);
            fma2(s01[r], pk2(qv.w, qv.w), kw);
        }
    }
    __syncthreads();

    const float scale = g_scale[h];
    const float kn0 = kn[lane], kn1 = kn[lane + 32];
    const float* rb = g_rel_bias + h * (NTOK * NTOK);
    const float* mk = mask + (size_t)w * (NTOK * NTOK);

    const int swz0 = (lane & 7) << 3;
    const int swz1 = ((lane + 32) & 7) << 3;
    #pragma unroll
    for (int r = 0; r < 8; r++) {
        int n = wid*8 + r;
        float qsc = qn[n] * scale;
        int off = n*64 + lane;
        float2 sv = upk2(s01[r]);
        float x0 = sv.x*qsc*kn0 + rb[off]      + mk[off];
        float x1 = sv.y*qsc*kn1 + rb[off + 32] + mk[off + 32];
        float mx = fmaxf(x0, x1);
        #pragma unroll
        for (int o = 16; o > 0; o >>= 1)
            mx = fmaxf(mx, __shfl_xor_sync(0xffffffffu, mx, o));
        float e0 = __expf(x0 - mx);
        float e1 = __expf(x1 - mx);
        float sm = e0 + e1;
        #pragma unroll
        for (int o = 16; o > 0; o >>= 1)
            sm += __shfl_xor_sync(0xffffffffu, sm, o);
        float inv = 1.0f / sm;
        PT(lane,      n ^ swz0) = e0 * inv;
        PT(lane + 32, n ^ swz1) = e1 * inv;
    }
    __syncthreads();

    u64t o01 = pk2(0.f,0.f), o23 = pk2(0.f,0.f), o45 = pk2(0.f,0.f), o67 = pk2(0.f,0.f);
    #pragma unroll
    for (int m = 0; m < 64; m++) {
        float vm = vs[m][lane];
        u64t vmd = pk2(vm, vm);
        const float* prow = &PT(m, (wid ^ (m & 7)) * 8);
        float4 p0 = *(const float4*)(prow);
        float4 p1 = *(const float4*)(prow + 4);
        fma2(o01, pk2(p0.x, p0.y), vmd);
        fma2(o23, pk2(p0.z, p0.w), vmd);
        fma2(o45, pk2(p1.x, p1.y), vmd);
        fma2(o67, pk2(p1.z, p1.w), vmd);
    }
    float o[8];
    { float2 t = upk2(o01); o[0] = t.x; o[1] = t.y; }
    { float2 t = upk2(o23); o[2] = t.x; o[3] = t.y; }
    { float2 t = upk2(o45); o[4] = t.x; o[5] = t.y; }
    { float2 t = upk2(o67); o[6] = t.x; o[7] = t.y; }

    #pragma unroll
    for (int r = 0; r < 8; r++) {
        size_t oi = (size_t)(b*NTOK + wid*8 + r) * DIM + h*HDIM + lane;
        __nv_bfloat16 hi = __float2bfloat16(o[r]);
        __nv_bfloat16 lo = __float2bfloat16(o[r] - __bfloat162float(hi));
        aoh[oi] = hi;
        aol[oi] = lo;
    }
    #undef QS
    #undef KS
    #undef PT
}

// ---------------------------------------------------------------------------
// Launch order keeps gemm_bf16_128<0> at position #4 (the ncu slot).
// ---------------------------------------------------------------------------
extern "C" void kernel_launch(void* const* d_in, const int* in_sizes, int n_in,
                              void* d_out, int out_size)
{
    const float* x           = (const float*)d_in[0];
    const float* mask        = (const float*)d_in[1];
    const float* qkv_w       = (const float*)d_in[2];
    const float* q_bias      = (const float*)d_in[3];
    const float* v_bias      = (const float*)d_in[4];
    const float* logit_scale = (const float*)d_in[5];
    const float* cpb_w1      = (const float*)d_in[6];
    const float* cpb_b1      = (const float*)d_in[7];
    const float* cpb_w2      = (const float*)d_in[8];
    const float* proj_w      = (const float*)d_in[9];
    const float* proj_b      = (const float*)d_in[10];
    const float* rel_table   = (const float*)d_in[11];
    const int*   rel_idx     = (const int*)d_in[12];
    float*       out         = (float*)d_out;

    float *qkv_ptr;
    __nv_bfloat16 *xh, *xl, *wh, *wl, *ph, *pl, *aoh, *aol;
    cudaGetSymbolAddress((void**)&qkv_ptr, g_qkv);
    cudaGetSymbolAddress((void**)&xh, g_xh);   cudaGetSymbolAddress((void**)&xl, g_xl);
    cudaGetSymbolAddress((void**)&wh, g_wh);   cudaGetSymbolAddress((void**)&wl, g_wl);
    cudaGetSymbolAddress((void**)&ph, g_ph);   cudaGetSymbolAddress((void**)&pl, g_pl);
    cudaGetSymbolAddress((void**)&aoh, g_aoh); cudaGetSymbolAddress((void**)&aol, g_aol);

    cudaFuncSetAttribute(gemm_bf16_128<0>, cudaFuncAttributeMaxDynamicSharedMemorySize, GEMM_SMEM);
    cudaFuncSetAttribute(gemm_bf16_128<1>, cudaFuncAttributeMaxDynamicSharedMemorySize, GEMM_SMEM);

    // 1-3: splits
    split_f32<<<(ROWS*DIM/4 + 255)/256, 256>>>(x, xh, xl, ROWS*DIM/4);
    split_f32<<<(QKVCOLS*DIM/4 + 255)/256, 256>>>(qkv_w, wh, wl, QKVCOLS*DIM/4);
    split_f32<<<(DIM*DIM/4 + 255)/256, 256>>>(proj_w, ph, pl, DIM*DIM/4);

    // 4: QKV GEMM  <-- profiled slot
    gemm_bf16_128<0><<<dim3(QKVCOLS/128, ROWS/128), 512, GEMM_SMEM>>>(
        xh, xl, wh, wl, q_bias, v_bias, qkv_ptr, QKVCOLS);

    // 5-6: CPB
    cpb_mlp_kernel<<<225, 512>>>(rel_table, cpb_w1, cpb_b1, cpb_w2);
    cpb_expand_kernel<<<256, 256>>>(rel_idx, logit_scale);

    // 7: attention
    attn_kernel<<<dim3(BATCH, HEADS), 256>>>(qkv_ptr, mask, aoh, aol);

    // 8: proj GEMM
    gemm_bf16_128<1><<<dim3(DIM/128, ROWS/128), 512, GEMM_SMEM>>>(
        aoh, aol, ph, pl, proj_b, nullptr, out, DIM);
}

// round 16
// speedup vs baseline: 1.2058x; 1.0300x over previous
#include <cuda_runtime.h>
#include <cuda_bf16.h>
#include <math.h>
#include <stdint.h>

#define BATCH   1024
#define NTOK    64
#define DIM     512
#define HEADS   16
#define HDIM    32
#define NW      64
#define ROWS    (BATCH * NTOK)      // 65536
#define QKVCOLS (3 * DIM)           // 1536

// ---------------- device scratch ----------------
__device__ __align__(16) float         g_qkv[(size_t)ROWS * QKVCOLS];
__device__ __align__(16) __nv_bfloat16 g_xh[(size_t)ROWS * DIM];
__device__ __align__(16) __nv_bfloat16 g_xl[(size_t)ROWS * DIM];
__device__ __align__(16) __nv_bfloat16 g_wh[(size_t)QKVCOLS * DIM];
__device__ __align__(16) __nv_bfloat16 g_wl[(size_t)QKVCOLS * DIM];
__device__ __align__(16) __nv_bfloat16 g_ph[(size_t)DIM * DIM];
__device__ __align__(16) __nv_bfloat16 g_pl[(size_t)DIM * DIM];
__device__ __align__(16) __nv_bfloat16 g_aoh[(size_t)ROWS * DIM];
__device__ __align__(16) __nv_bfloat16 g_aol[(size_t)ROWS * DIM];
__device__ float g_bias_table[225 * HEADS];
__device__ float g_rel_bias[HEADS * NTOK * NTOK];
__device__ float g_scale[HEADS];

// ---------------- helpers ----------------
__device__ __forceinline__ uint32_t smem_u32(const void* p) {
    uint32_t a;
    asm("{ .reg .u64 t; cvta.to.shared.u64 t, %1; cvt.u32.u64 %0, t; }" : "=r"(a) : "l"(p));
    return a;
}

#define LDSM4(r0,r1,r2,r3, addr) \
    asm volatile("ldmatrix.sync.aligned.m8n8.x4.shared.b16 {%0,%1,%2,%3}, [%4];" \
        : "=r"(r0),"=r"(r1),"=r"(r2),"=r"(r3) : "r"(addr))

#define MMA_BF16(d, a, b) \
    asm volatile("mma.sync.aligned.m16n8k16.row.col.f32.bf16.bf16.f32 " \
        "{%0,%1,%2,%3}, {%4,%5,%6,%7}, {%8,%9}, {%0,%1,%2,%3};" \
        : "+f"(d[0]),"+f"(d[1]),"+f"(d[2]),"+f"(d[3]) \
        : "r"(a[0]),"r"(a[1]),"r"(a[2]),"r"(a[3]),"r"(b[0]),"r"(b[1]))

#define CP16(dst, src) \
    asm volatile("cp.async.ca.shared.global [%0], [%1], 16;" :: "r"(dst), "l"(src))
#define CP_COMMIT() asm volatile("cp.async.commit_group;" ::: "memory")
#define CP_WAIT1()  asm volatile("cp.async.wait_group 1;" ::: "memory")

__device__ __forceinline__ uint32_t packbf(float a, float b) {
    __nv_bfloat162 t;
    t.x = __float2bfloat16(a);
    t.y = __float2bfloat16(b);
    return *(uint32_t*)&t;
}

// ---------------- fp32 -> bf16 hi/lo split ----------------
__global__ void split_f32(const float* __restrict__ in,
                          __nv_bfloat16* __restrict__ hi,
                          __nv_bfloat16* __restrict__ lo, int n4)
{
    int i = blockIdx.x * blockDim.x + threadIdx.x;
    if (i >= n4) return;
    float4 v = ((const float4*)in)[i];
    __nv_bfloat16 h[4], l[4];
    float x[4] = {v.x, v.y, v.z, v.w};
    #pragma unroll
    for (int j = 0; j < 4; j++) {
        h[j] = __float2bfloat16(x[j]);
        l[j] = __float2bfloat16(x[j] - __bfloat162float(h[j]));
    }
    ((uint2*)hi)[i] = *(uint2*)h;
    ((uint2*)lo)[i] = *(uint2*)l;
}

// ---------------- CPB MLP ----------------
__global__ void cpb_mlp_kernel(const float* __restrict__ tbl,
                               const float* __restrict__ w1,
                               const float* __restrict__ b1,
                               const float* __restrict__ w2)
{
    int i = blockIdx.x, j = threadIdx.x;
    __shared__ float hid[512];
    float hv = tbl[i*2+0] * w1[j*2+0] + tbl[i*2+1] * w1[j*2+1] + b1[j];
    hid[j] = fmaxf(hv, 0.0f);
    __syncthreads();
    int warp = j >> 5, lane = j & 31;
    float s = 0.0f;
    #pragma unroll
    for (int c = lane; c < 512; c += 32) s += hid[c] * w2[warp*512 + c];
    #pragma unroll
    for (int off = 16; off > 0; off >>= 1) s += __shfl_xor_sync(0xffffffffu, s, off);
    if (lane == 0) g_bias_table[i*HEADS + warp] = s;
}

__global__ void cpb_expand_kernel(const int* __restrict__ idx,
                                  const float* __restrict__ logit_scale)
{
    int g = blockIdx.x * 256 + threadIdx.x;
    int h = g >> 12, nm = g & 4095;
    float v = g_bias_table[idx[nm]*HEADS + h];
    g_rel_bias[g] = 16.0f / (1.0f + expf(-v));
    if (g < HEADS) g_scale[g] = expf(fminf(logit_scale[g], 4.60517018598809136804f));
}

// ---------------------------------------------------------------------------
// split-bf16 GEMM (NT): R15-proven. BM=BN=128, BK=32, 512 thr, 3-stage
// cp.async, one barrier per k-iter, warp-parity ks skew.
// ---------------------------------------------------------------------------
#define AB_SZ 10240
#define STG (4 * AB_SZ)          // 40960
#define GEMM_SMEM (3 * STG)      // 122880

template <int MODE>   // 0: qkv bias (q|0|v), 1: proj bias
__global__ __launch_bounds__(512, 1) void gemm_bf16_128(
    const __nv_bfloat16* __restrict__ Ah, const __nv_bfloat16* __restrict__ Al,
    const __nv_bfloat16* __restrict__ Bh, const __nv_bfloat16* __restrict__ Bl,
    const float* __restrict__ bias0, const float* __restrict__ bias1,
    float* __restrict__ C, int N)
{
    extern __shared__ char smem[];

    const int tid  = threadIdx.x;
    const int bm   = blockIdx.y * 128;
    const int bn   = blockIdx.x * 128;
    const int wid  = tid >> 5, lane = tid & 31;
    const int wm   = (wid & 3) * 32;
    const int wn   = (wid >> 2) * 32;
    const int ks0  = wid & 1;

    const uint32_t sbase = smem_u32(smem);

    float acc[2][4][4];
    #pragma unroll
    for (int a = 0; a < 2; a++)
        #pragma unroll
        for (int b = 0; b < 4; b++)
            #pragma unroll
            for (int c = 0; c < 4; c++) acc[a][b][c] = 0.0f;

    const int lrow = tid >> 2;
    const int lq   = tid & 3;
    auto load_stage = [&](int kt, int buf) {
        const uint32_t sb = sbase + buf * STG;
        const size_t goff_a = (size_t)(bm + lrow) * 512 + kt * 32 + lq * 8;
        const size_t goff_b = (size_t)(bn + lrow) * 512 + kt * 32 + lq * 8;
        const uint32_t d = sb + (uint32_t)(lrow * 80 + lq * 16);
        CP16(d,             (const char*)Ah + goff_a * 2);
        CP16(d +   AB_SZ,   (const char*)Al + goff_a * 2);
        CP16(d + 2*AB_SZ,   (const char*)Bh + goff_b * 2);
        CP16(d + 3*AB_SZ,   (const char*)Bl + goff_b * 2);
        CP_COMMIT();
    };

    load_stage(0, 0);
    load_stage(1, 1);

    for (int kt = 0; kt < 16; kt++) {
        const int buf = kt % 3;
        CP_WAIT1();
        __syncthreads();

        if (kt + 2 < 16) load_stage(kt + 2, (kt + 2) % 3);
        else CP_COMMIT();

        const uint32_t sb  = sbase + buf * STG;
        const uint32_t aAh = sb;
        const uint32_t aAl = sb +   AB_SZ;
        const uint32_t aBh = sb + 2*AB_SZ;
        const uint32_t aBl = sb + 3*AB_SZ;

        #pragma unroll
        for (int i = 0; i < 2; i++) {
            const int ks = ks0 ^ i;
            const int kb = ks * 16;
            uint32_t ah[2][4], al[2][4], bh[4][2], bl[4][2];
            #pragma unroll
            for (int mt = 0; mt < 2; mt++) {
                int row = wm + mt*16 + (lane & 15);
                int col = kb + (lane >> 4) * 8;
                uint32_t off = (uint32_t)(row*80 + col*2);
                LDSM4(ah[mt][0], ah[mt][1], ah[mt][2], ah[mt][3], aAh + off);
                LDSM4(al[mt][0], al[mt][1], al[mt][2], al[mt][3], aAl + off);
            }
            #pragma unroll
            for (int np = 0; np < 2; np++) {
                int g = lane >> 3;
                int row = wn + np*16 + (lane & 7) + ((g >> 1) & 1) * 8;
                int col = kb + (g & 1) * 8;
                uint32_t off = (uint32_t)(row*80 + col*2);
                LDSM4(bh[2*np][0], bh[2*np][1], bh[2*np+1][0], bh[2*np+1][1], aBh + off);
                LDSM4(bl[2*np][0], bl[2*np][1], bl[2*np+1][0], bl[2*np+1][1], aBl + off);
            }
            #pragma unroll
            for (int mt = 0; mt < 2; mt++)
                #pragma unroll
                for (int nt = 0; nt < 4; nt++) {
                    MMA_BF16(acc[mt][nt], ah[mt], bh[nt]);
                    MMA_BF16(acc[mt][nt], ah[mt], bl[nt]);
                    MMA_BF16(acc[mt][nt], al[mt], bh[nt]);
                }
        }
    }

    #pragma unroll
    for (int mt = 0; mt < 2; mt++) {
        #pragma unroll
        for (int nt = 0; nt < 4; nt++) {
            int row = bm + wm + mt*16 + (lane >> 2);
            int col = bn + wn + nt*8 + (lane & 3)*2;
            float b0, b1;
            if (MODE == 0) {
                b0 = (col   < 512) ? bias0[col]   : ((col   < 1024) ? 0.0f : bias1[col - 1024]);
                b1 = (col+1 < 512) ? bias0[col+1] : ((col+1 < 1024) ? 0.0f : bias1[col+1 - 1024]);
            } else {
                b0 = bias0[col]; b1 = bias0[col+1];
            }
            float* p0 = C + (size_t)row * N + col;
            float* p1 = C + (size_t)(row + 8) * N + col;
            p0[0] = acc[mt][nt][0] + b0;  p0[1] = acc[mt][nt][1] + b1;
            p1[0] = acc[mt][nt][2] + b0;  p1[1] = acc[mt][nt][3] + b1;
        }
    }
}

// ---------------------------------------------------------------------------
// Tensor-core window attention per (b,h), 128 threads (4 warps).
// S = 3-term bf16 mma (qh kh + qh kl + ql kh); softmax on C-frags in regs;
// P repacked to A-frags (hi/lo) -> PV = 3-term mma. 2 block barriers.
// ---------------------------------------------------------------------------
__global__ __launch_bounds__(128) void attn_tc(const float* __restrict__ qkv,
                                               const float* __restrict__ mask,
                                               __nv_bfloat16* __restrict__ aoh,
                                               __nv_bfloat16* __restrict__ aol)
{
    const int b = blockIdx.x;
    const int h = blockIdx.y;
    const int w = b & (NW - 1);
    const int tid  = threadIdx.x;
    const int wid  = tid >> 5, lane = tid & 31;

    __shared__ __align__(16) __nv_bfloat16 sqh[64*40], sql[64*40];   // 80B rows
    __shared__ __align__(16) __nv_bfloat16 skh[64*40], skl[64*40];
    __shared__ __align__(16) __nv_bfloat16 svh[32*72], svl[32*72];   // V^T 144B rows
    __shared__ float qn[64], kn[64];

    // ---- stage q,k (row layout) and v (transposed) as bf16 hi/lo ----
    const float* base = qkv + (size_t)b * NTOK * QKVCOLS + h * HDIM;
    for (int e = tid; e < 512; e += 128) {        // e: float4 index in 64x32
        int n  = e >> 3;
        int dq = (e & 7) * 4;
        const float* r = base + (size_t)n * QKVCOLS + dq;
        float4 qv = *(const float4*)(r);
        float4 kv = *(const float4*)(r + 512);
        float4 vv = *(const float4*)(r + 1024);
        float qa[4] = {qv.x, qv.y, qv.z, qv.w};
        float ka[4] = {kv.x, kv.y, kv.z, kv.w};
        float va[4] = {vv.x, vv.y, vv.z, vv.w};
        #pragma unroll
        for (int j = 0; j < 4; j++) {
            __nv_bfloat16 hh;
            hh = __float2bfloat16(qa[j]);
            sqh[n*40 + dq + j] = hh;
            sql[n*40 + dq + j] = __float2bfloat16(qa[j] - __bfloat162float(hh));
            hh = __float2bfloat16(ka[j]);
            skh[n*40 + dq + j] = hh;
            skl[n*40 + dq + j] = __float2bfloat16(ka[j] - __bfloat162float(hh));
            hh = __float2bfloat16(va[j]);
            svh[(dq + j)*72 + n] = hh;
            svl[(dq + j)*72 + n] = __float2bfloat16(va[j] - __bfloat162float(hh));
        }
    }
    __syncthreads();

    // ---- inverse norms (reconstruct hi+lo) ----
    {
        int n = tid & 63;
        bool isq = tid < 64;
        const __nv_bfloat16* ph_ = isq ? (sqh + n*40) : (skh + n*40);
        const __nv_bfloat16* pl_ = isq ? (sql + n*40) : (skl + n*40);
        float s = 0.0f;
        #pragma unroll
        for (int d = 0; d < 32; d++) {
            float x = __bfloat162float(ph_[d]) + __bfloat162float(pl_[d]);
            s = fmaf(x, x, s);
        }
        float inv = 1.0f / fmaxf(sqrtf(s), 1e-12f);
        if (isq) qn[n] = inv; else kn[n] = inv;
    }
    __syncthreads();

    const uint32_t aQh = smem_u32(sqh), aQl = smem_u32(sql);
    const uint32_t aKh = smem_u32(skh), aKl = smem_u32(skl);
    const uint32_t aVh = smem_u32(svh), aVl = smem_u32(svl);

    // ---- S: warp owns rows wid*16..+15, all 64 cols (8 n8-frags) ----
    float sacc[8][4];
    #pragma unroll
    for (int f = 0; f < 8; f++)
        #pragma unroll
        for (int j = 0; j < 4; j++) sacc[f][j] = 0.0f;

    #pragma unroll
    for (int kk = 0; kk < 2; kk++) {
        uint32_t ah[4], al[4], bh[8][2], bl[8][2];
        {
            int row = wid*16 + (lane & 15);
            int col = kk*16 + (lane >> 4) * 8;
            uint32_t off = (uint32_t)(row*80 + col*2);
            LDSM4(ah[0], ah[1], ah[2], ah[3], aQh + off);
            LDSM4(al[0], al[1], al[2], al[3], aQl + off);
        }
        #pragma unroll
        for (int np = 0; np < 4; np++) {
            int g = lane >> 3;
            int row = np*16 + (lane & 7) + ((g >> 1) & 1) * 8;
            int col = kk*16 + (g & 1) * 8;
            uint32_t off = (uint32_t)(row*80 + col*2);
            LDSM4(bh[2*np][0], bh[2*np][1], bh[2*np+1][0], bh[2*np+1][1], aKh + off);
            LDSM4(bl[2*np][0], bl[2*np][1], bl[2*np+1][0], bl[2*np+1][1], aKl + off);
        }
        #pragma unroll
        for (int f = 0; f < 8; f++) {
            MMA_BF16(sacc[f], ah, bh[f]);
            MMA_BF16(sacc[f], ah, bl[f]);
            MMA_BF16(sacc[f], al, bh[f]);
        }
    }

    // ---- softmax on C-frag layout ----
    const float scale = g_scale[h];
    const int r0 = wid*16 + (lane >> 2);
    const int r1 = r0 + 8;
    const int c0 = (lane & 3) * 2;
    const float qs0 = qn[r0] * scale;
    const float qs1 = qn[r1] * scale;
    const float* rb = g_rel_bias + h * (NTOK * NTOK);
    const float* mk = mask + (size_t)w * (NTOK * NTOK);

    #pragma unroll
    for (int f = 0; f < 8; f++) {
        int cA = f*8 + c0, cB = cA + 1;
        float knA = kn[cA], knB = kn[cB];
        sacc[f][0] = sacc[f][0]*qs0*knA + rb[r0*64 + cA] + mk[r0*64 + cA];
        sacc[f][1] = sacc[f][1]*qs0*knB + rb[r0*64 + cB] + mk[r0*64 + cB];
        sacc[f][2] = sacc[f][2]*qs1*knA + rb[r1*64 + cA] + mk[r1*64 + cA];
        sacc[f][3] = sacc[f][3]*qs1*knB + rb[r1*64 + cB] + mk[r1*64 + cB];
    }
    float m0 = -1e30f, m1 = -1e30f;
    #pragma unroll
    for (int f = 0; f < 8; f++) {
        m0 = fmaxf(m0, fmaxf(sacc[f][0], sacc[f][1]));
        m1 = fmaxf(m1, fmaxf(sacc[f][2], sacc[f][3]));
    }
    m0 = fmaxf(m0, __shfl_xor_sync(0xffffffffu, m0, 1));
    m0 = fmaxf(m0, __shfl_xor_sync(0xffffffffu, m0, 2));
    m1 = fmaxf(m1, __shfl_xor_sync(0xffffffffu, m1, 1));
    m1 = fmaxf(m1, __shfl_xor_sync(0xffffffffu, m1, 2));
    float s0 = 0.0f, s1 = 0.0f;
    #pragma unroll
    for (int f = 0; f < 8; f++) {
        sacc[f][0] = __expf(sacc[f][0] - m0);
        sacc[f][1] = __expf(sacc[f][1] - m0);
        sacc[f][2] = __expf(sacc[f][2] - m1);
        sacc[f][3] = __expf(sacc[f][3] - m1);
        s0 += sacc[f][0] + sacc[f][1];
        s1 += sacc[f][2] + sacc[f][3];
    }
    s0 += __shfl_xor_sync(0xffffffffu, s0, 1);
    s0 += __shfl_xor_sync(0xffffffffu, s0, 2);
    s1 += __shfl_xor_sync(0xffffffffu, s1, 1);
    s1 += __shfl_xor_sync(0xffffffffu, s1, 2);
    const float i0 = 1.0f / s0, i1 = 1.0f / s1;
    #pragma unroll
    for (int f = 0; f < 8; f++) {
        sacc[f][0] *= i0; sacc[f][1] *= i0;
        sacc[f][2] *= i1; sacc[f][3] *= i1;
    }

    // ---- repack P C-frags into A-frags (hi/lo) ----
    // A[kk] = { S[2kk]c01, S[2kk]c23, S[2kk+1]c01, S[2kk+1]c23 }
    uint32_t pah[4][4], pal[4][4];
    #pragma unroll
    for (int kk = 0; kk < 4; kk++) {
        #pragma unroll
        for (int half = 0; half < 2; half++) {      // 0: frag 2kk, 1: frag 2kk+1
            int f = 2*kk + half;
            float v0 = sacc[f][0], v1 = sacc[f][1];
            float v2 = sacc[f][2], v3 = sacc[f][3];
            uint32_t h01 = packbf(v0, v1);
            uint32_t h23 = packbf(v2, v3);
            __nv_bfloat162 t01 = *(__nv_bfloat162*)&h01;
            __nv_bfloat162 t23 = *(__nv_bfloat162*)&h23;
            uint32_t l01 = packbf(v0 - __bfloat162float(t01.x), v1 - __bfloat162float(t01.y));
            uint32_t l23 = packbf(v2 - __bfloat162float(t23.x), v3 - __bfloat162float(t23.y));
            pah[kk][half*2 + 0] = h01;   // a0 / a2
            pah[kk][half*2 + 1] = h23;   // a1 / a3  (rows +8)
            pal[kk][half*2 + 0] = l01;
            pal[kk][half*2 + 1] = l23;
        }
        // reorder to {a0,a1,a2,a3} = {f0c01, f0c23, f1c01, f1c23}
        // pah[kk] currently = {f0c01, f0c23, f1c01, f1c23} -> already correct:
        // a0 = rows r, k0-7 = f0c01 ; a1 = rows r+8, k0-7 = f0c23 ;
        // a2 = rows r, k8-15 = f1c01 ; a3 = rows r+8, k8-15 = f1c23.
    }

    // ---- PV: O[16 x 32] per warp, 4 n8-frags, 4 k16 steps ----
    float oacc[4][4];
    #pragma unroll
    for (int nt = 0; nt < 4; nt++)
        #pragma unroll
        for (int j = 0; j < 4; j++) oacc[nt][j] = 0.0f;

    #pragma unroll
    for (int kk = 0; kk < 4; kk++) {
        uint32_t vbh[4][2], vbl[4][2];
        #pragma unroll
        for (int np = 0; np < 2; np++) {
            int g = lane >> 3;
            int row = np*16 + (lane & 7) + ((g >> 1) & 1) * 8;   // dim rows 0..31
            int col = kk*16 + (g & 1) * 8;                       // token cols
            uint32_t off = (uint32_t)(row*144 + col*2);
            LDSM4(vbh[2*np][0], vbh[2*np][1], vbh[2*np+1][0], vbh[2*np+1][1], aVh + off);
            LDSM4(vbl[2*np][0], vbl[2*np][1], vbl[2*np+1][0], vbl[2*np+1][1], aVl + off);
        }
        #pragma unroll
        for (int nt = 0; nt < 4; nt++) {
            MMA_BF16(oacc[nt], pah[kk], vbh[nt]);
            MMA_BF16(oacc[nt], pah[kk], vbl[nt]);
            MMA_BF16(oacc[nt], pal[kk], vbh[nt]);
        }
    }

    // ---- write O as bf16 hi/lo ----
    #pragma unroll
    for (int nt = 0; nt < 4; nt++) {
        int col = h*HDIM + nt*8 + c0;
        size_t oi0 = (size_t)(b*NTOK + r0) * DIM + col;
        size_t oi1 = (size_t)(b*NTOK + r1) * DIM + col;
        #pragma unroll
        for (int j = 0; j < 2; j++) {
            float v = oacc[nt][j];
            __nv_bfloat16 hh = __float2bfloat16(v);
            aoh[oi0 + j] = hh;
            aol[oi0 + j] = __float2bfloat16(v - __bfloat162float(hh));
            float v2 = oacc[nt][2 + j];
            __nv_bfloat16 h2 = __float2bfloat16(v2);
            aoh[oi1 + j] = h2;
            aol[oi1 + j] = __float2bfloat16(v2 - __bfloat162float(h2));
        }
    }
}

// ---------------------------------------------------------------------------
extern "C" void kernel_launch(void* const* d_in, const int* in_sizes, int n_in,
                              void* d_out, int out_size)
{
    const float* x           = (const float*)d_in[0];
    const float* mask        = (const float*)d_in[1];
    const float* qkv_w       = (const float*)d_in[2];
    const float* q_bias      = (const float*)d_in[3];
    const float* v_bias      = (const float*)d_in[4];
    const float* logit_scale = (const float*)d_in[5];
    const float* cpb_w1      = (const float*)d_in[6];
    const float* cpb_b1      = (const float*)d_in[7];
    const float* cpb_w2      = (const float*)d_in[8];
    const float* proj_w      = (const float*)d_in[9];
    const float* proj_b      = (const float*)d_in[10];
    const float* rel_table   = (const float*)d_in[11];
    const int*   rel_idx     = (const int*)d_in[12];
    float*       out         = (float*)d_out;

    float *qkv_ptr;
    __nv_bfloat16 *xh, *xl, *wh, *wl, *ph, *pl, *aoh, *aol;
    cudaGetSymbolAddress((void**)&qkv_ptr, g_qkv);
    cudaGetSymbolAddress((void**)&xh, g_xh);   cudaGetSymbolAddress((void**)&xl, g_xl);
    cudaGetSymbolAddress((void**)&wh, g_wh);   cudaGetSymbolAddress((void**)&wl, g_wl);
    cudaGetSymbolAddress((void**)&ph, g_ph);   cudaGetSymbolAddress((void**)&pl, g_pl);
    cudaGetSymbolAddress((void**)&aoh, g_aoh); cudaGetSymbolAddress((void**)&aol, g_aol);

    cudaFuncSetAttribute(gemm_bf16_128<0>, cudaFuncAttributeMaxDynamicSharedMemorySize, GEMM_SMEM);
    cudaFuncSetAttribute(gemm_bf16_128<1>, cudaFuncAttributeMaxDynamicSharedMemorySize, GEMM_SMEM);

    // 1-3: splits
    split_f32<<<(ROWS*DIM/4 + 255)/256, 256>>>(x, xh, xl, ROWS*DIM/4);
    split_f32<<<(QKVCOLS*DIM/4 + 255)/256, 256>>>(qkv_w, wh, wl, QKVCOLS*DIM/4);
    split_f32<<<(DIM*DIM/4 + 255)/256, 256>>>(proj_w, ph, pl, DIM*DIM/4);

    // 4: QKV GEMM  <-- profiled slot
    gemm_bf16_128<0><<<dim3(QKVCOLS/128, ROWS/128), 512, GEMM_SMEM>>>(
        xh, xl, wh, wl, q_bias, v_bias, qkv_ptr, QKVCOLS);

    // 5-6: CPB
    cpb_mlp_kernel<<<225, 512>>>(rel_table, cpb_w1, cpb_b1, cpb_w2);
    cpb_expand_kernel<<<256, 256>>>(rel_idx, logit_scale);

    // 7: tensor-core attention
    attn_tc<<<dim3(BATCH, HEADS), 128>>>(qkv_ptr, mask, aoh, aol);

    // 8: proj GEMM
    gemm_bf16_128<1><<<dim3(DIM/128, ROWS/128), 512, GEMM_SMEM>>>(
        aoh, aol, ph, pl, proj_b, nullptr, out, DIM);
}

// round 17
// speedup vs baseline: 1.2376x; 1.0263x over previous
#include <cuda_runtime.h>
#include <cuda_bf16.h>
#include <math.h>
#include <stdint.h>

#define BATCH   1024
#define NTOK    64
#define DIM     512
#define HEADS   16
#define HDIM    32
#define NW      64
#define ROWS    (BATCH * NTOK)      // 65536
#define QKVCOLS (3 * DIM)           // 1536

// ---------------- device scratch ----------------
__device__ __align__(16) __nv_bfloat16 g_qkvh[(size_t)ROWS * QKVCOLS]; // qkv hi
__device__ __align__(16) __nv_bfloat16 g_qkvl[(size_t)ROWS * QKVCOLS]; // qkv lo
__device__ __align__(16) __nv_bfloat16 g_xh[(size_t)ROWS * DIM];
__device__ __align__(16) __nv_bfloat16 g_xl[(size_t)ROWS * DIM];
__device__ __align__(16) __nv_bfloat16 g_wh[(size_t)QKVCOLS * DIM];
__device__ __align__(16) __nv_bfloat16 g_wl[(size_t)QKVCOLS * DIM];
__device__ __align__(16) __nv_bfloat16 g_ph[(size_t)DIM * DIM];
__device__ __align__(16) __nv_bfloat16 g_pl[(size_t)DIM * DIM];
__device__ __align__(16) __nv_bfloat16 g_aoh[(size_t)ROWS * DIM];
__device__ __align__(16) __nv_bfloat16 g_aol[(size_t)ROWS * DIM];
__device__ float g_bias_table[225 * HEADS];
__device__ float g_rel_bias[HEADS * NTOK * NTOK];
__device__ float g_scale[HEADS];

// ---------------- helpers ----------------
__device__ __forceinline__ uint32_t smem_u32(const void* p) {
    uint32_t a;
    asm("{ .reg .u64 t; cvta.to.shared.u64 t, %1; cvt.u32.u64 %0, t; }" : "=r"(a) : "l"(p));
    return a;
}

#define LDSM4(r0,r1,r2,r3, addr) \
    asm volatile("ldmatrix.sync.aligned.m8n8.x4.shared.b16 {%0,%1,%2,%3}, [%4];" \
        : "=r"(r0),"=r"(r1),"=r"(r2),"=r"(r3) : "r"(addr))

#define MMA_BF16(d, a, b) \
    asm volatile("mma.sync.aligned.m16n8k16.row.col.f32.bf16.bf16.f32 " \
        "{%0,%1,%2,%3}, {%4,%5,%6,%7}, {%8,%9}, {%0,%1,%2,%3};" \
        : "+f"(d[0]),"+f"(d[1]),"+f"(d[2]),"+f"(d[3]) \
        : "r"(a[0]),"r"(a[1]),"r"(a[2]),"r"(a[3]),"r"(b[0]),"r"(b[1]))

#define CP16(dst, src) \
    asm volatile("cp.async.ca.shared.global [%0], [%1], 16;" :: "r"(dst), "l"(src))
#define CP_COMMIT() asm volatile("cp.async.commit_group;" ::: "memory")
#define CP_WAIT1()  asm volatile("cp.async.wait_group 1;" ::: "memory")

__device__ __forceinline__ uint32_t packbf(float a, float b) {
    __nv_bfloat162 t;
    t.x = __float2bfloat16(a);
    t.y = __float2bfloat16(b);
    return *(uint32_t*)&t;
}

// ---------------- fp32 -> bf16 hi/lo split ----------------
__global__ void split_f32(const float* __restrict__ in,
                          __nv_bfloat16* __restrict__ hi,
                          __nv_bfloat16* __restrict__ lo, int n4)
{
    int i = blockIdx.x * blockDim.x + threadIdx.x;
    if (i >= n4) return;
    float4 v = ((const float4*)in)[i];
    __nv_bfloat16 h[4], l[4];
    float x[4] = {v.x, v.y, v.z, v.w};
    #pragma unroll
    for (int j = 0; j < 4; j++) {
        h[j] = __float2bfloat16(x[j]);
        l[j] = __float2bfloat16(x[j] - __bfloat162float(h[j]));
    }
    ((uint2*)hi)[i] = *(uint2*)h;
    ((uint2*)lo)[i] = *(uint2*)l;
}

// ---------------- CPB MLP ----------------
__global__ void cpb_mlp_kernel(const float* __restrict__ tbl,
                               const float* __restrict__ w1,
                               const float* __restrict__ b1,
                               const float* __restrict__ w2)
{
    int i = blockIdx.x, j = threadIdx.x;
    __shared__ float hid[512];
    float hv = tbl[i*2+0] * w1[j*2+0] + tbl[i*2+1] * w1[j*2+1] + b1[j];
    hid[j] = fmaxf(hv, 0.0f);
    __syncthreads();
    int warp = j >> 5, lane = j & 31;
    float s = 0.0f;
    #pragma unroll
    for (int c = lane; c < 512; c += 32) s += hid[c] * w2[warp*512 + c];
    #pragma unroll
    for (int off = 16; off > 0; off >>= 1) s += __shfl_xor_sync(0xffffffffu, s, off);
    if (lane == 0) g_bias_table[i*HEADS + warp] = s;
}

__global__ void cpb_expand_kernel(const int* __restrict__ idx,
                                  const float* __restrict__ logit_scale)
{
    int g = blockIdx.x * 256 + threadIdx.x;
    int h = g >> 12, nm = g & 4095;
    float v = g_bias_table[idx[nm]*HEADS + h];
    g_rel_bias[g] = 16.0f / (1.0f + expf(-v));
    if (g < HEADS) g_scale[g] = expf(fminf(logit_scale[g], 4.60517018598809136804f));
}

// ---------------------------------------------------------------------------
// split-bf16 GEMM (NT): R15-proven loop. BM=BN=128, BK=32, 512 thr, 3-stage
// cp.async, one barrier per k-iter, warp-parity ks skew.
// MODE 0: qkv bias (q|0|v), epilogue writes bf16 hi/lo to (Ch, Cl).
// MODE 1: proj bias, epilogue writes fp32 to C.
// ---------------------------------------------------------------------------
#define AB_SZ 10240
#define STG (4 * AB_SZ)          // 40960
#define GEMM_SMEM (3 * STG)      // 122880

template <int MODE>
__global__ __launch_bounds__(512, 1) void gemm_bf16_128(
    const __nv_bfloat16* __restrict__ Ah, const __nv_bfloat16* __restrict__ Al,
    const __nv_bfloat16* __restrict__ Bh, const __nv_bfloat16* __restrict__ Bl,
    const float* __restrict__ bias0, const float* __restrict__ bias1,
    float* __restrict__ C, __nv_bfloat16* __restrict__ Ch,
    __nv_bfloat16* __restrict__ Cl, int N)
{
    extern __shared__ char smem[];

    const int tid  = threadIdx.x;
    const int bm   = blockIdx.y * 128;
    const int bn   = blockIdx.x * 128;
    const int wid  = tid >> 5, lane = tid & 31;
    const int wm   = (wid & 3) * 32;
    const int wn   = (wid >> 2) * 32;
    const int ks0  = wid & 1;

    const uint32_t sbase = smem_u32(smem);

    float acc[2][4][4];
    #pragma unroll
    for (int a = 0; a < 2; a++)
        #pragma unroll
        for (int b = 0; b < 4; b++)
            #pragma unroll
            for (int c = 0; c < 4; c++) acc[a][b][c] = 0.0f;

    const int lrow = tid >> 2;
    const int lq   = tid & 3;
    auto load_stage = [&](int kt, int buf) {
        const uint32_t sb = sbase + buf * STG;
        const size_t goff_a = (size_t)(bm + lrow) * 512 + kt * 32 + lq * 8;
        const size_t goff_b = (size_t)(bn + lrow) * 512 + kt * 32 + lq * 8;
        const uint32_t d = sb + (uint32_t)(lrow * 80 + lq * 16);
        CP16(d,             (const char*)Ah + goff_a * 2);
        CP16(d +   AB_SZ,   (const char*)Al + goff_a * 2);
        CP16(d + 2*AB_SZ,   (const char*)Bh + goff_b * 2);
        CP16(d + 3*AB_SZ,   (const char*)Bl + goff_b * 2);
        CP_COMMIT();
    };

    load_stage(0, 0);
    load_stage(1, 1);

    for (int kt = 0; kt < 16; kt++) {
        const int buf = kt % 3;
        CP_WAIT1();
        __syncthreads();

        if (kt + 2 < 16) load_stage(kt + 2, (kt + 2) % 3);
        else CP_COMMIT();

        const uint32_t sb  = sbase + buf * STG;
        const uint32_t aAh = sb;
        const uint32_t aAl = sb +   AB_SZ;
        const uint32_t aBh = sb + 2*AB_SZ;
        const uint32_t aBl = sb + 3*AB_SZ;

        #pragma unroll
        for (int i = 0; i < 2; i++) {
            const int ks = ks0 ^ i;
            const int kb = ks * 16;
            uint32_t ah[2][4], al[2][4], bh[4][2], bl[4][2];
            #pragma unroll
            for (int mt = 0; mt < 2; mt++) {
                int row = wm + mt*16 + (lane & 15);
                int col = kb + (lane >> 4) * 8;
                uint32_t off = (uint32_t)(row*80 + col*2);
                LDSM4(ah[mt][0], ah[mt][1], ah[mt][2], ah[mt][3], aAh + off);
                LDSM4(al[mt][0], al[mt][1], al[mt][2], al[mt][3], aAl + off);
            }
            #pragma unroll
            for (int np = 0; np < 2; np++) {
                int g = lane >> 3;
                int row = wn + np*16 + (lane & 7) + ((g >> 1) & 1) * 8;
                int col = kb + (g & 1) * 8;
                uint32_t off = (uint32_t)(row*80 + col*2);
                LDSM4(bh[2*np][0], bh[2*np][1], bh[2*np+1][0], bh[2*np+1][1], aBh + off);
                LDSM4(bl[2*np][0], bl[2*np][1], bl[2*np+1][0], bl[2*np+1][1], aBl + off);
            }
            #pragma unroll
            for (int mt = 0; mt < 2; mt++)
                #pragma unroll
                for (int nt = 0; nt < 4; nt++) {
                    MMA_BF16(acc[mt][nt], ah[mt], bh[nt]);
                    MMA_BF16(acc[mt][nt], ah[mt], bl[nt]);
                    MMA_BF16(acc[mt][nt], al[mt], bh[nt]);
                }
        }
    }

    #pragma unroll
    for (int mt = 0; mt < 2; mt++) {
        #pragma unroll
        for (int nt = 0; nt < 4; nt++) {
            int row = bm + wm + mt*16 + (lane >> 2);
            int col = bn + wn + nt*8 + (lane & 3)*2;
            float b0, b1;
            if (MODE == 0) {
                b0 = (col   < 512) ? bias0[col]   : ((col   < 1024) ? 0.0f : bias1[col - 1024]);
                b1 = (col+1 < 512) ? bias0[col+1] : ((col+1 < 1024) ? 0.0f : bias1[col+1 - 1024]);
            } else {
                b0 = bias0[col]; b1 = bias0[col+1];
            }
            float v0 = acc[mt][nt][0] + b0, v1 = acc[mt][nt][1] + b1;
            float v2 = acc[mt][nt][2] + b0, v3 = acc[mt][nt][3] + b1;
            if (MODE == 0) {
                // bf16 hi/lo packed stores
                size_t i0 = (size_t)row * N + col;
                size_t i1 = (size_t)(row + 8) * N + col;
                uint32_t h01 = packbf(v0, v1);
                uint32_t h23 = packbf(v2, v3);
                __nv_bfloat162 t01 = *(__nv_bfloat162*)&h01;
                __nv_bfloat162 t23 = *(__nv_bfloat162*)&h23;
                uint32_t l01 = packbf(v0 - __bfloat162float(t01.x), v1 - __bfloat162float(t01.y));
                uint32_t l23 = packbf(v2 - __bfloat162float(t23.x), v3 - __bfloat162float(t23.y));
                *(uint32_t*)(Ch + i0) = h01;
                *(uint32_t*)(Ch + i1) = h23;
                *(uint32_t*)(Cl + i0) = l01;
                *(uint32_t*)(Cl + i1) = l23;
            } else {
                float* p0 = C + (size_t)row * N + col;
                float* p1 = C + (size_t)(row + 8) * N + col;
                p0[0] = v0;  p0[1] = v1;
                p1[0] = v2;  p1[1] = v3;
            }
        }
    }
}

// ---------------------------------------------------------------------------
// Tensor-core window attention per (b,h), 128 threads (4 warps).
// Inputs are pre-split bf16 hi/lo -> staging is pure vector copies + a bf16
// V transpose. S = 3-term mma, softmax on C-frags, P repack -> 3-term PV.
// ---------------------------------------------------------------------------
__global__ __launch_bounds__(128) void attn_tc(const __nv_bfloat16* __restrict__ qkvh,
                                               const __nv_bfloat16* __restrict__ qkvl,
                                               const float* __restrict__ mask,
                                               __nv_bfloat16* __restrict__ aoh,
                                               __nv_bfloat16* __restrict__ aol)
{
    const int b = blockIdx.x;
    const int h = blockIdx.y;
    const int w = b & (NW - 1);
    const int tid  = threadIdx.x;
    const int wid  = tid >> 5, lane = tid & 31;

    __shared__ __align__(16) __nv_bfloat16 sqh[64*40], sql[64*40];   // 80B rows
    __shared__ __align__(16) __nv_bfloat16 skh[64*40], skl[64*40];
    __shared__ __align__(16) __nv_bfloat16 svh[32*72], svl[32*72];   // V^T 144B rows
    __shared__ float qn[64], kn[64];

    const __nv_bfloat16* gh = qkvh + (size_t)b * NTOK * QKVCOLS + h * HDIM;
    const __nv_bfloat16* gl = qkvl + (size_t)b * NTOK * QKVCOLS + h * HDIM;

    // q/k: 64 rows x 4 chunks of 16B per matrix — pure uint4 copies
    #pragma unroll
    for (int e = tid; e < 256; e += 128) {
        int n = e >> 2, c = (e & 3) * 8;
        const size_t go = (size_t)n * QKVCOLS + c;
        *(uint4*)&sqh[n*40 + c] = *(const uint4*)(gh + go);
        *(uint4*)&sql[n*40 + c] = *(const uint4*)(gl + go);
        *(uint4*)&skh[n*40 + c] = *(const uint4*)(gh + 512 + go);
        *(uint4*)&skl[n*40 + c] = *(const uint4*)(gl + 512 + go);
    }
    // v transpose: 64 tokens x 16 d-pairs, bf16x2 loads
    #pragma unroll
    for (int e = tid; e < 1024; e += 128) {
        int n = e >> 4, d = (e & 15) * 2;
        const size_t go = (size_t)n * QKVCOLS + 1024 + d;
        __nv_bfloat162 th = *(const __nv_bfloat162*)(gh + go);
        __nv_bfloat162 tl = *(const __nv_bfloat162*)(gl + go);
        svh[d*72 + n]     = th.x;
        svh[(d+1)*72 + n] = th.y;
        svl[d*72 + n]     = tl.x;
        svl[(d+1)*72 + n] = tl.y;
    }
    __syncthreads();

    // inverse norms (reconstruct hi+lo)
    {
        int n = tid & 63;
        bool isq = tid < 64;
        const __nv_bfloat16* ph_ = isq ? (sqh + n*40) : (skh + n*40);
        const __nv_bfloat16* pl_ = isq ? (sql + n*40) : (skl + n*40);
        float s = 0.0f;
        #pragma unroll
        for (int d = 0; d < 32; d++) {
            float x = __bfloat162float(ph_[d]) + __bfloat162float(pl_[d]);
            s = fmaf(x, x, s);
        }
        float inv = 1.0f / fmaxf(sqrtf(s), 1e-12f);
        if (isq) qn[n] = inv; else kn[n] = inv;
    }
    __syncthreads();

    const uint32_t aQh = smem_u32(sqh), aQl = smem_u32(sql);
    const uint32_t aKh = smem_u32(skh), aKl = smem_u32(skl);
    const uint32_t aVh = smem_u32(svh), aVl = smem_u32(svl);

    // S: warp owns rows wid*16..+15, all 64 cols (8 n8-frags)
    float sacc[8][4];
    #pragma unroll
    for (int f = 0; f < 8; f++)
        #pragma unroll
        for (int j = 0; j < 4; j++) sacc[f][j] = 0.0f;

    #pragma unroll
    for (int kk = 0; kk < 2; kk++) {
        uint32_t ah[4], al[4], bh[8][2], bl[8][2];
        {
            int row = wid*16 + (lane & 15);
            int col = kk*16 + (lane >> 4) * 8;
            uint32_t off = (uint32_t)(row*80 + col*2);
            LDSM4(ah[0], ah[1], ah[2], ah[3], aQh + off);
            LDSM4(al[0], al[1], al[2], al[3], aQl + off);
        }
        #pragma unroll
        for (int np = 0; np < 4; np++) {
            int g = lane >> 3;
            int row = np*16 + (lane & 7) + ((g >> 1) & 1) * 8;
            int col = kk*16 + (g & 1) * 8;
            uint32_t off = (uint32_t)(row*80 + col*2);
            LDSM4(bh[2*np][0], bh[2*np][1], bh[2*np+1][0], bh[2*np+1][1], aKh + off);
            LDSM4(bl[2*np][0], bl[2*np][1], bl[2*np+1][0], bl[2*np+1][1], aKl + off);
        }
        #pragma unroll
        for (int f = 0; f < 8; f++) {
            MMA_BF16(sacc[f], ah, bh[f]);
            MMA_BF16(sacc[f], ah, bl[f]);
            MMA_BF16(sacc[f], al, bh[f]);
        }
    }

    // softmax on C-frag layout
    const float scale = g_scale[h];
    const int r0 = wid*16 + (lane >> 2);
    const int r1 = r0 + 8;
    const int c0 = (lane & 3) * 2;
    const float qs0 = qn[r0] * scale;
    const float qs1 = qn[r1] * scale;
    const float* rb = g_rel_bias + h * (NTOK * NTOK);
    const float* mk = mask + (size_t)w * (NTOK * NTOK);

    #pragma unroll
    for (int f = 0; f < 8; f++) {
        int cA = f*8 + c0, cB = cA + 1;
        float knA = kn[cA], knB = kn[cB];
        sacc[f][0] = sacc[f][0]*qs0*knA + rb[r0*64 + cA] + mk[r0*64 + cA];
        sacc[f][1] = sacc[f][1]*qs0*knB + rb[r0*64 + cB] + mk[r0*64 + cB];
        sacc[f][2] = sacc[f][2]*qs1*knA + rb[r1*64 + cA] + mk[r1*64 + cA];
        sacc[f][3] = sacc[f][3]*qs1*knB + rb[r1*64 + cB] + mk[r1*64 + cB];
    }
    float m0 = -1e30f, m1 = -1e30f;
    #pragma unroll
    for (int f = 0; f < 8; f++) {
        m0 = fmaxf(m0, fmaxf(sacc[f][0], sacc[f][1]));
        m1 = fmaxf(m1, fmaxf(sacc[f][2], sacc[f][3]));
    }
    m0 = fmaxf(m0, __shfl_xor_sync(0xffffffffu, m0, 1));
    m0 = fmaxf(m0, __shfl_xor_sync(0xffffffffu, m0, 2));
    m1 = fmaxf(m1, __shfl_xor_sync(0xffffffffu, m1, 1));
    m1 = fmaxf(m1, __shfl_xor_sync(0xffffffffu, m1, 2));
    float s0 = 0.0f, s1 = 0.0f;
    #pragma unroll
    for (int f = 0; f < 8; f++) {
        sacc[f][0] = __expf(sacc[f][0] - m0);
        sacc[f][1] = __expf(sacc[f][1] - m0);
        sacc[f][2] = __expf(sacc[f][2] - m1);
        sacc[f][3] = __expf(sacc[f][3] - m1);
        s0 += sacc[f][0] + sacc[f][1];
        s1 += sacc[f][2] + sacc[f][3];
    }
    s0 += __shfl_xor_sync(0xffffffffu, s0, 1);
    s0 += __shfl_xor_sync(0xffffffffu, s0, 2);
    s1 += __shfl_xor_sync(0xffffffffu, s1, 1);
    s1 += __shfl_xor_sync(0xffffffffu, s1, 2);
    const float i0 = 1.0f / s0, i1 = 1.0f / s1;
    #pragma unroll
    for (int f = 0; f < 8; f++) {
        sacc[f][0] *= i0; sacc[f][1] *= i0;
        sacc[f][2] *= i1; sacc[f][3] *= i1;
    }

    // repack P C-frags into A-frags (hi/lo)
    uint32_t pah[4][4], pal[4][4];
    #pragma unroll
    for (int kk = 0; kk < 4; kk++) {
        #pragma unroll
        for (int half = 0; half < 2; half++) {
            int f = 2*kk + half;
            float v0 = sacc[f][0], v1 = sacc[f][1];
            float v2 = sacc[f][2], v3 = sacc[f][3];
            uint32_t h01 = packbf(v0, v1);
            uint32_t h23 = packbf(v2, v3);
            __nv_bfloat162 t01 = *(__nv_bfloat162*)&h01;
            __nv_bfloat162 t23 = *(__nv_bfloat162*)&h23;
            uint32_t l01 = packbf(v0 - __bfloat162float(t01.x), v1 - __bfloat162float(t01.y));
            uint32_t l23 = packbf(v2 - __bfloat162float(t23.x), v3 - __bfloat162float(t23.y));
            pah[kk][half*2 + 0] = h01;
            pah[kk][half*2 + 1] = h23;
            pal[kk][half*2 + 0] = l01;
            pal[kk][half*2 + 1] = l23;
        }
    }

    // PV: O[16 x 32] per warp, 4 n8-frags, 4 k16 steps
    float oacc[4][4];
    #pragma unroll
    for (int nt = 0; nt < 4; nt++)
        #pragma unroll
        for (int j = 0; j < 4; j++) oacc[nt][j] = 0.0f;

    #pragma unroll
    for (int kk = 0; kk < 4; kk++) {
        uint32_t vbh[4][2], vbl[4][2];
        #pragma unroll
        for (int np = 0; np < 2; np++) {
            int g = lane >> 3;
            int row = np*16 + (lane & 7) + ((g >> 1) & 1) * 8;
            int col = kk*16 + (g & 1) * 8;
            uint32_t off = (uint32_t)(row*144 + col*2);
            LDSM4(vbh[2*np][0], vbh[2*np][1], vbh[2*np+1][0], vbh[2*np+1][1], aVh + off);
            LDSM4(vbl[2*np][0], vbl[2*np][1], vbl[2*np+1][0], vbl[2*np+1][1], aVl + off);
        }
        #pragma unroll
        for (int nt = 0; nt < 4; nt++) {
            MMA_BF16(oacc[nt], pah[kk], vbh[nt]);
            MMA_BF16(oacc[nt], pah[kk], vbl[nt]);
            MMA_BF16(oacc[nt], pal[kk], vbh[nt]);
        }
    }

    // write O as bf16 hi/lo
    #pragma unroll
    for (int nt = 0; nt < 4; nt++) {
        int col = h*HDIM + nt*8 + c0;
        size_t oi0 = (size_t)(b*NTOK + r0) * DIM + col;
        size_t oi1 = (size_t)(b*NTOK + r1) * DIM + col;
        uint32_t h01 = packbf(oacc[nt][0], oacc[nt][1]);
        __nv_bfloat162 t01 = *(__nv_bfloat162*)&h01;
        uint32_t l01 = packbf(oacc[nt][0] - __bfloat162float(t01.x),
                              oacc[nt][1] - __bfloat162float(t01.y));
        uint32_t h23 = packbf(oacc[nt][2], oacc[nt][3]);
        __nv_bfloat162 t23 = *(__nv_bfloat162*)&h23;
        uint32_t l23 = packbf(oacc[nt][2] - __bfloat162float(t23.x),
                              oacc[nt][3] - __bfloat162float(t23.y));
        *(uint32_t*)(aoh + oi0) = h01;
        *(uint32_t*)(aol + oi0) = l01;
        *(uint32_t*)(aoh + oi1) = h23;
        *(uint32_t*)(aol + oi1) = l23;
    }
}

// ---------------------------------------------------------------------------
extern "C" void kernel_launch(void* const* d_in, const int* in_sizes, int n_in,
                              void* d_out, int out_size)
{
    const float* x           = (const float*)d_in[0];
    const float* mask        = (const float*)d_in[1];
    const float* qkv_w       = (const float*)d_in[2];
    const float* q_bias      = (const float*)d_in[3];
    const float* v_bias      = (const float*)d_in[4];
    const float* logit_scale = (const float*)d_in[5];
    const float* cpb_w1      = (const float*)d_in[6];
    const float* cpb_b1      = (const float*)d_in[7];
    const float* cpb_w2      = (const float*)d_in[8];
    const float* proj_w      = (const float*)d_in[9];
    const float* proj_b      = (const float*)d_in[10];
    const float* rel_table   = (const float*)d_in[11];
    const int*   rel_idx     = (const int*)d_in[12];
    float*       out         = (float*)d_out;

    __nv_bfloat16 *qkvh, *qkvl, *xh, *xl, *wh, *wl, *ph, *pl, *aoh, *aol;
    cudaGetSymbolAddress((void**)&qkvh, g_qkvh); cudaGetSymbolAddress((void**)&qkvl, g_qkvl);
    cudaGetSymbolAddress((void**)&xh, g_xh);   cudaGetSymbolAddress((void**)&xl, g_xl);
    cudaGetSymbolAddress((void**)&wh, g_wh);   cudaGetSymbolAddress((void**)&wl, g_wl);
    cudaGetSymbolAddress((void**)&ph, g_ph);   cudaGetSymbolAddress((void**)&pl, g_pl);
    cudaGetSymbolAddress((void**)&aoh, g_aoh); cudaGetSymbolAddress((void**)&aol, g_aol);

    cudaFuncSetAttribute(gemm_bf16_128<0>, cudaFuncAttributeMaxDynamicSharedMemorySize, GEMM_SMEM);
    cudaFuncSetAttribute(gemm_bf16_128<1>, cudaFuncAttributeMaxDynamicSharedMemorySize, GEMM_SMEM);

    // 1-3: splits
    split_f32<<<(ROWS*DIM/4 + 255)/256, 256>>>(x, xh, xl, ROWS*DIM/4);
    split_f32<<<(QKVCOLS*DIM/4 + 255)/256, 256>>>(qkv_w, wh, wl, QKVCOLS*DIM/4);
    split_f32<<<(DIM*DIM/4 + 255)/256, 256>>>(proj_w, ph, pl, DIM*DIM/4);

    // 4: QKV GEMM (writes bf16 hi/lo)  <-- profiled slot
    gemm_bf16_128<0><<<dim3(QKVCOLS/128, ROWS/128), 512, GEMM_SMEM>>>(
        xh, xl, wh, wl, q_bias, v_bias, nullptr, qkvh, qkvl, QKVCOLS);

    // 5-6: CPB
    cpb_mlp_kernel<<<225, 512>>>(rel_table, cpb_w1, cpb_b1, cpb_w2);
    cpb_expand_kernel<<<256, 256>>>(rel_idx, logit_scale);

    // 7: tensor-core attention
    attn_tc<<<dim3(BATCH, HEADS), 128>>>(qkvh, qkvl, mask, aoh, aol);

    // 8: proj GEMM (fp32 out)
    gemm_bf16_128<1><<<dim3(DIM/128, ROWS/128), 512, GEMM_SMEM>>>(
        aoh, aol, ph, pl, proj_b, nullptr, out, nullptr, nullptr, DIM);
}